// round 2
// baseline (speedup 1.0000x reference)
#include <cuda_runtime.h>
#include <cuda_bf16.h>
#include <cstdint>

#define NTOK 4096
#define NCH  64

// Scratch (static device globals; no dynamic allocation allowed)
__device__ float g_q[2][4][NCH][NTOK];   // 8 MB
__device__ float g_k[2][4][NCH][NTOK];   // 8 MB
__device__ float g_v[2][4][NCH][NTOK];   // 8 MB
__device__ float g_m[2][4][NTOK];
__device__ float g_z[2][4][NTOK];
__device__ float g_o[2][4][NCH][NTOK];   // 8 MB

// ---------------------------------------------------------------------------
// Kernel 1: 1x1 conv projection  out[b][o][n] = sum_c W[o][c] x[b][c][n] + bias[o]
// grid (8 n-splits, 4 batches), block 256
// ---------------------------------------------------------------------------
__global__ void proj_kernel(const float* __restrict__ x,
                            const float* __restrict__ W,
                            const float* __restrict__ bias,
                            int br, int which) {
    __shared__ float Wt[64][64];   // Wt[c][o]
    __shared__ float xs[64][64];   // xs[c][n_local]
    __shared__ float bs[64];

    int t = threadIdx.x;
    int b = blockIdx.y;
    int n0 = blockIdx.x * 512;

    float* out;
    if (which == 0)      out = &g_q[br][0][0][0];
    else if (which == 1) out = &g_k[br][0][0][0];
    else                 out = &g_v[br][0][0][0];
    out += (size_t)b * NCH * NTOK;

    for (int idx = t; idx < 64 * 64; idx += 256) {
        int o = idx >> 6, c = idx & 63;
        Wt[c][o] = W[idx];
    }
    if (t < 64) bs[t] = bias[t];
    __syncthreads();

    const float* xb = x + (size_t)b * NCH * NTOK;
    int tx = t & 15, ty = t >> 4;   // o = ty*4.., n = tx*4..

    for (int nc = 0; nc < 512; nc += 64) {
        __syncthreads();
        for (int idx = t; idx < 64 * 16; idx += 256) {
            int c = idx >> 4, n4 = idx & 15;
            *(float4*)&xs[c][n4 * 4] =
                *(const float4*)&xb[c * NTOK + n0 + nc + n4 * 4];
        }
        __syncthreads();

        float acc[4][4] = {};
        #pragma unroll 8
        for (int c = 0; c < 64; c++) {
            float wv[4], xv[4];
            *(float4*)wv = *(float4*)&Wt[c][ty * 4];
            *(float4*)xv = *(float4*)&xs[c][tx * 4];
            #pragma unroll
            for (int i = 0; i < 4; i++)
                #pragma unroll
                for (int j = 0; j < 4; j++)
                    acc[i][j] += wv[i] * xv[j];
        }
        #pragma unroll
        for (int i = 0; i < 4; i++) {
            int o = ty * 4 + i;
            float bb = bs[o];
            float4 r = make_float4(acc[i][0] + bb, acc[i][1] + bb,
                                   acc[i][2] + bb, acc[i][3] + bb);
            *(float4*)&out[o * NTOK + n0 + nc + tx * 4] = r;
        }
    }
}

// ---------------------------------------------------------------------------
// Kernel 2: per-row softmax stats (m, Z) via online max/sum over all j
// grid (32 i-tiles of 128, 2 branches, 4 batches), block 256
// dynamic smem: Qs[64][128] + Ks[64][128] = 64 KB
// ---------------------------------------------------------------------------
__global__ void rowstats_kernel() {
    extern __shared__ float sm[];
    float (*Qs)[128] = (float(*)[128])sm;
    float (*Ks)[128] = (float(*)[128])(sm + 64 * 128);

    int t = threadIdx.x;
    int i0 = blockIdx.x * 128;
    int br = blockIdx.y, b = blockIdx.z;

    const float* Qg = &g_q[br][b][0][0];
    const float* Kg = &g_k[br][b][0][0];

    for (int idx = t; idx < 64 * 32; idx += 256) {
        int c = idx >> 5, i4 = idx & 31;
        *(float4*)&Qs[c][i4 * 4] = *(const float4*)&Qg[c * NTOK + i0 + i4 * 4];
    }

    int tx = t & 15, ty = t >> 4;   // rows i = ty*8.., cols j = tx*8..
    float m_run[8], z_run[8];
    #pragma unroll
    for (int r = 0; r < 8; r++) { m_run[r] = -1e30f; z_run[r] = 0.f; }

    for (int jt = 0; jt < 32; jt++) {
        __syncthreads();
        for (int idx = t; idx < 64 * 32; idx += 256) {
            int c = idx >> 5, j4 = idx & 31;
            *(float4*)&Ks[c][j4 * 4] =
                *(const float4*)&Kg[c * NTOK + jt * 128 + j4 * 4];
        }
        __syncthreads();

        float acc[8][8] = {};
        #pragma unroll 8
        for (int c = 0; c < 64; c++) {
            float a[8], bv[8];
            *(float4*)a       = *(float4*)&Qs[c][ty * 8];
            *(float4*)(a + 4) = *(float4*)&Qs[c][ty * 8 + 4];
            *(float4*)bv       = *(float4*)&Ks[c][tx * 8];
            *(float4*)(bv + 4) = *(float4*)&Ks[c][tx * 8 + 4];
            #pragma unroll
            for (int r = 0; r < 8; r++)
                #pragma unroll
                for (int j = 0; j < 8; j++)
                    acc[r][j] += a[r] * bv[j];
        }

        #pragma unroll
        for (int r = 0; r < 8; r++) {
            float tm = acc[r][0];
            #pragma unroll
            for (int j = 1; j < 8; j++) tm = fmaxf(tm, acc[r][j]);
            #pragma unroll
            for (int s = 1; s < 16; s <<= 1)
                tm = fmaxf(tm, __shfl_xor_sync(0xffffffffu, tm, s));
            float mn = fmaxf(m_run[r], tm);
            float ps = 0.f;
            #pragma unroll
            for (int j = 0; j < 8; j++) ps += __expf(acc[r][j] - mn);
            #pragma unroll
            for (int s = 1; s < 16; s <<= 1)
                ps += __shfl_xor_sync(0xffffffffu, ps, s);
            z_run[r] = z_run[r] * __expf(m_run[r] - mn) + ps;
            m_run[r] = mn;
        }
    }

    if (tx == 0) {
        #pragma unroll
        for (int r = 0; r < 8; r++) {
            g_m[br][b][i0 + ty * 8 + r] = m_run[r];
            g_z[br][b][i0 + ty * 8 + r] = z_run[r];
        }
    }
}

// ---------------------------------------------------------------------------
// Kernel 3: out[c][j] = sum_i (v[c][i]/Z[i]) * exp(s[i][j]-m[i])
// grid (32 j-tiles of 128, 2 branches, 4 batches), block 256
// per i-tile (64): recompute S block, exp+normalize into Ps, then PV GEMM
// dynamic smem: Ks[64][128] + Qs[64][64] + Vs[64][64] + Ps[64][132] + m/z
// ---------------------------------------------------------------------------
__global__ void attn_pv_kernel() {
    extern __shared__ float sm[];
    float (*Ks)[128] = (float(*)[128])sm;                        // 8192
    float (*Qs)[64]  = (float(*)[64])(sm + 64 * 128);            // 4096
    float (*Vs)[64]  = (float(*)[64])(sm + 64 * 128 + 4096);     // 4096
    float (*Ps)[132] = (float(*)[132])(sm + 64 * 128 + 8192);    // 8448
    float* msm = sm + 64 * 128 + 8192 + 64 * 132;                // 64
    float* rzs = msm + 64;                                       // 64

    int t = threadIdx.x;
    int j0 = blockIdx.x * 128;
    int br = blockIdx.y, b = blockIdx.z;

    const float* Qg = &g_q[br][b][0][0];
    const float* Kg = &g_k[br][b][0][0];
    const float* Vg = &g_v[br][b][0][0];

    for (int idx = t; idx < 64 * 32; idx += 256) {
        int c = idx >> 5, j4 = idx & 31;
        *(float4*)&Ks[c][j4 * 4] = *(const float4*)&Kg[c * NTOK + j0 + j4 * 4];
    }

    int tx = t & 15, ty = t >> 4;   // S-block: rows i = ty*4.., cols j = tx*8..
    int u = t & 31,  w = t >> 5;    // GEMM: cols j = u*4.., rows c = w*8..

    float oacc[8][4] = {};

    for (int it = 0; it < 64; it++) {
        int i0 = it * 64;
        __syncthreads();
        for (int idx = t; idx < 64 * 16; idx += 256) {
            int c = idx >> 4, i4 = idx & 15;
            *(float4*)&Qs[c][i4 * 4] = *(const float4*)&Qg[c * NTOK + i0 + i4 * 4];
            *(float4*)&Vs[c][i4 * 4] = *(const float4*)&Vg[c * NTOK + i0 + i4 * 4];
        }
        if (t < 64) {
            msm[t] = g_m[br][b][i0 + t];
            rzs[t] = 1.0f / g_z[br][b][i0 + t];
        }
        __syncthreads();

        // S block [64 x 128]
        float sacc[4][8] = {};
        #pragma unroll 8
        for (int c = 0; c < 64; c++) {
            float a[4], bv[8];
            *(float4*)a        = *(float4*)&Qs[c][ty * 4];
            *(float4*)bv       = *(float4*)&Ks[c][tx * 8];
            *(float4*)(bv + 4) = *(float4*)&Ks[c][tx * 8 + 4];
            #pragma unroll
            for (int r = 0; r < 4; r++)
                #pragma unroll
                for (int j = 0; j < 8; j++)
                    sacc[r][j] += a[r] * bv[j];
        }
        #pragma unroll
        for (int r = 0; r < 4; r++) {
            int i = ty * 4 + r;
            float mm = msm[i], rz = rzs[i];
            #pragma unroll
            for (int j = 0; j < 8; j++)
                sacc[r][j] = __expf(sacc[r][j] - mm) * rz;
            *(float4*)&Ps[i][tx * 8]     = *(float4*)&sacc[r][0];
            *(float4*)&Ps[i][tx * 8 + 4] = *(float4*)&sacc[r][4];
        }
        __syncthreads();

        // PV GEMM: oacc[cc][jj] += Vs[w*8+cc][i] * Ps[i][u*4+jj]
        #pragma unroll 4
        for (int i = 0; i < 64; i++) {
            float p4[4];
            *(float4*)p4 = *(float4*)&Ps[i][u * 4];
            #pragma unroll
            for (int cc = 0; cc < 8; cc++) {
                float vv = Vs[w * 8 + cc][i];
                #pragma unroll
                for (int jj = 0; jj < 4; jj++)
                    oacc[cc][jj] += vv * p4[jj];
            }
        }
    }

    float* Og = &g_o[br][b][0][0];
    #pragma unroll
    for (int cc = 0; cc < 8; cc++)
        *(float4*)&Og[(w * 8 + cc) * NTOK + j0 + u * 4] = *(float4*)&oacc[cc][0];
}

// ---------------------------------------------------------------------------
// Kernel 4: y[b][o][n] = b_f[o] + sum_{c<64} Wf[o][c]*g1*Oh[c][n]
//                               + sum_{c<64} Wf[o][64+c]*g2*Ol[c][n]
// grid (8 n-splits, 4 batches), block 256, dynamic smem 64.25 KB
// ---------------------------------------------------------------------------
__global__ void final_kernel(const float* __restrict__ Wf,
                             const float* __restrict__ bf,
                             const float* __restrict__ g1p,
                             const float* __restrict__ g2p,
                             float* __restrict__ y) {
    extern __shared__ float sm[];
    float (*Wt)[64] = (float(*)[64])sm;              // [128][64]  Wt[c][o]
    float (*cs)[64] = (float(*)[64])(sm + 128 * 64); // [128][64]  cs[c][n]
    float* bs = sm + 2 * 128 * 64;

    int t = threadIdx.x;
    int b = blockIdx.y;
    int n0 = blockIdx.x * 512;
    float gg1 = *g1p, gg2 = *g2p;

    for (int idx = t; idx < 64 * 128; idx += 256) {
        int o = idx >> 7, c = idx & 127;
        Wt[c][o] = Wf[idx];
    }
    if (t < 64) bs[t] = bf[t];
    __syncthreads();

    int tx = t & 15, ty = t >> 4;
    for (int nc = 0; nc < 512; nc += 64) {
        __syncthreads();
        for (int idx = t; idx < 128 * 16; idx += 256) {
            int c = idx >> 4, n4 = idx & 15;
            const float* src = (c < 64) ? &g_o[0][b][c][0] : &g_o[1][b][c - 64][0];
            float g = (c < 64) ? gg1 : gg2;
            float4 v4 = *(const float4*)&src[n0 + nc + n4 * 4];
            v4.x *= g; v4.y *= g; v4.z *= g; v4.w *= g;
            *(float4*)&cs[c][n4 * 4] = v4;
        }
        __syncthreads();

        float acc[4][4] = {};
        #pragma unroll 8
        for (int c = 0; c < 128; c++) {
            float wv[4], xv[4];
            *(float4*)wv = *(float4*)&Wt[c][ty * 4];
            *(float4*)xv = *(float4*)&cs[c][tx * 4];
            #pragma unroll
            for (int i = 0; i < 4; i++)
                #pragma unroll
                for (int j = 0; j < 4; j++)
                    acc[i][j] += wv[i] * xv[j];
        }
        #pragma unroll
        for (int i = 0; i < 4; i++) {
            int o = ty * 4 + i;
            float bb = bs[o];
            float4 r = make_float4(acc[i][0] + bb, acc[i][1] + bb,
                                   acc[i][2] + bb, acc[i][3] + bb);
            *(float4*)&y[(size_t)b * NCH * NTOK + o * NTOK + n0 + nc + tx * 4] = r;
        }
    }
}

// ---------------------------------------------------------------------------
extern "C" void kernel_launch(void* const* d_in, const int* in_sizes, int n_in,
                              void* d_out, int out_size) {
    const float* x  = (const float*)d_in[0];
    // W/bias in order: qh,kh,vh, ql,kl,vl at indices (1,2),(3,4)...(11,12)
    const float* g1 = (const float*)d_in[13];
    const float* g2 = (const float*)d_in[14];
    const float* Wf = (const float*)d_in[15];
    const float* bf = (const float*)d_in[16];
    float* y = (float*)d_out;

    const int smem2 = 2 * 64 * 128 * 4;                              // 65536
    const int smem3 = (64 * 128 + 2 * 64 * 64 + 64 * 132 + 128) * 4; // 99840
    const int smem4 = (2 * 128 * 64 + 64) * 4;                       // 65792

    cudaFuncSetAttribute(rowstats_kernel, cudaFuncAttributeMaxDynamicSharedMemorySize, smem2);
    cudaFuncSetAttribute(attn_pv_kernel,  cudaFuncAttributeMaxDynamicSharedMemorySize, smem3);
    cudaFuncSetAttribute(final_kernel,    cudaFuncAttributeMaxDynamicSharedMemorySize, smem4);

    // 6 QKV projections
    for (int mi = 0; mi < 6; mi++) {
        const float* W = (const float*)d_in[1 + 2 * mi];
        const float* bb = (const float*)d_in[2 + 2 * mi];
        proj_kernel<<<dim3(8, 4), 256>>>(x, W, bb, mi / 3, mi % 3);
    }

    rowstats_kernel<<<dim3(32, 2, 4), 256, smem2>>>();
    attn_pv_kernel<<<dim3(32, 2, 4), 256, smem3>>>();
    final_kernel<<<dim3(8, 4), 256, smem4>>>(Wf, bf, g1, g2, y);
}

// round 4
// speedup vs baseline: 2.8682x; 2.8682x over previous
#include <cuda_runtime.h>
#include <cuda_bf16.h>
#include <cstdint>

#define NTOK 4096
#define L2E  1.4426950408889634f
#define PIT  72          // smem pitch in bf16 elements
#define PITB 144         // smem pitch in bytes

// ---------------- scratch ----------------
__device__ __nv_bfloat16 g_qth[2][4][NTOK][64];
__device__ __nv_bfloat16 g_qtl[2][4][NTOK][64];
__device__ __nv_bfloat16 g_kth[2][4][NTOK][64];
__device__ __nv_bfloat16 g_ktl[2][4][NTOK][64];
__device__ __nv_bfloat16 g_vh [2][4][64][NTOK];
__device__ __nv_bfloat16 g_vl [2][4][64][NTOK];
__device__ float g_c[2][4][NTOK];
__device__ float g_o[2][4][64][NTOK];

// ---------------- helpers ----------------
__device__ __forceinline__ uint32_t smem_u32(const void* p) {
    uint32_t a;
    asm("{ .reg .u64 t; cvta.to.shared.u64 t, %1; cvt.u32.u64 %0, t; }" : "=r"(a) : "l"(p));
    return a;
}
__device__ __forceinline__ float ex2f(float x) {
    float r; asm("ex2.approx.ftz.f32 %0, %1;" : "=f"(r) : "f"(x)); return r;
}
__device__ __forceinline__ void ldsm4(uint32_t* r, uint32_t a) {
    asm volatile("ldmatrix.sync.aligned.m8n8.x4.shared.b16 {%0,%1,%2,%3}, [%4];"
                 : "=r"(r[0]), "=r"(r[1]), "=r"(r[2]), "=r"(r[3]) : "r"(a));
}
__device__ __forceinline__ void ldsm2(uint32_t* r, uint32_t a) {
    asm volatile("ldmatrix.sync.aligned.m8n8.x2.shared.b16 {%0,%1}, [%2];"
                 : "=r"(r[0]), "=r"(r[1]) : "r"(a));
}
__device__ __forceinline__ void mma_bf16(float* c, const uint32_t* a, const uint32_t* b) {
    asm volatile("mma.sync.aligned.m16n8k16.row.col.f32.bf16.bf16.f32 "
                 "{%0,%1,%2,%3}, {%4,%5,%6,%7}, {%8,%9}, {%0,%1,%2,%3};"
                 : "+f"(c[0]), "+f"(c[1]), "+f"(c[2]), "+f"(c[3])
                 : "r"(a[0]), "r"(a[1]), "r"(a[2]), "r"(a[3]), "r"(b[0]), "r"(b[1]));
}
__device__ __forceinline__ uint32_t pack2(float a, float b) {
    __nv_bfloat16 ha = __float2bfloat16(a), hb = __float2bfloat16(b);
    return (uint32_t)__bfloat16_as_ushort(ha) | ((uint32_t)__bfloat16_as_ushort(hb) << 16);
}

// ---------------------------------------------------------------------------
// Kernel 1: fused projections -> bf16 hi/lo in MMA-ready (k-contiguous) layouts
// grid (8 n-splits, 4 batches, 6 mats), block 256, dyn smem ~50.3KB
// ---------------------------------------------------------------------------
struct ProjArgs { const float* W[6]; const float* B[6]; };

__global__ void __launch_bounds__(256) proj_kernel(const float* __restrict__ x, ProjArgs pa) {
    extern __shared__ char dsm[];
    float* Wt = (float*)dsm;                 // [64][64] Wt[c][o]
    float* xs = Wt + 4096;                   // [64][64] xs[c][n]
    float* bs = xs + 4096;                   // [64]
    __nv_bfloat16* tsh = (__nv_bfloat16*)(bs + 64);  // [64][PIT]
    __nv_bfloat16* tsl = tsh + 64 * PIT;

    int t = threadIdx.x;
    int b = blockIdx.y;
    int n0 = blockIdx.x * 512;
    int z = blockIdx.z, br = z / 3, which = z % 3;
    const float* W = pa.W[z];
    const float* bias = pa.B[z];

    for (int idx = t; idx < 64 * 64; idx += 256) {
        int o = idx >> 6, c = idx & 63;
        Wt[c * 64 + o] = W[idx];
    }
    if (t < 64) bs[t] = bias[t];
    __syncthreads();

    const float* xb = x + (size_t)b * 64 * NTOK;
    int tx = t & 15, ty = t >> 4;

    __nv_bfloat16 (*th)[64] = (which == 0) ? g_qth[br][b] : g_kth[br][b];
    __nv_bfloat16 (*tl)[64] = (which == 0) ? g_qtl[br][b] : g_ktl[br][b];

    for (int nc = 0; nc < 512; nc += 64) {
        __syncthreads();
        for (int idx = t; idx < 64 * 16; idx += 256) {
            int c = idx >> 4, n4 = idx & 15;
            *(float4*)&xs[c * 64 + n4 * 4] = *(const float4*)&xb[c * NTOK + n0 + nc + n4 * 4];
        }
        __syncthreads();

        float acc[4][4] = {};
        #pragma unroll 8
        for (int c = 0; c < 64; c++) {
            float wv[4], xv[4];
            *(float4*)wv = *(float4*)&Wt[c * 64 + ty * 4];
            *(float4*)xv = *(float4*)&xs[c * 64 + tx * 4];
            #pragma unroll
            for (int i = 0; i < 4; i++)
                #pragma unroll
                for (int j = 0; j < 4; j++)
                    acc[i][j] += wv[i] * xv[j];
        }

        if (which < 2) {
            // transpose via smem, then coalesced 16B stores
            #pragma unroll
            for (int j = 0; j < 4; j++) {
                int nl = tx * 4 + j;
                #pragma unroll
                for (int i = 0; i < 4; i++) {
                    int o = ty * 4 + i;
                    float v = acc[i][j] + bs[o];
                    __nv_bfloat16 h = __float2bfloat16(v);
                    tsh[nl * PIT + o] = h;
                    tsl[nl * PIT + o] = __float2bfloat16(v - __bfloat162float(h));
                }
            }
            __syncthreads();
            for (int idx = t; idx < 64 * 8; idx += 256) {
                int row = idx >> 3, c8 = idx & 7;
                *(uint4*)&th[n0 + nc + row][c8 * 8] = *(uint4*)&tsh[row * PIT + c8 * 8];
                *(uint4*)&tl[n0 + nc + row][c8 * 8] = *(uint4*)&tsl[row * PIT + c8 * 8];
            }
        } else {
            #pragma unroll
            for (int i = 0; i < 4; i++) {
                int o = ty * 4 + i;
                float bb = bs[o];
                float v0 = acc[i][0] + bb, v1 = acc[i][1] + bb;
                float v2 = acc[i][2] + bb, v3 = acc[i][3] + bb;
                __nv_bfloat16 h0 = __float2bfloat16(v0), h1 = __float2bfloat16(v1);
                __nv_bfloat16 h2 = __float2bfloat16(v2), h3 = __float2bfloat16(v3);
                uint2 hp, lp;
                hp.x = (uint32_t)__bfloat16_as_ushort(h0) | ((uint32_t)__bfloat16_as_ushort(h1) << 16);
                hp.y = (uint32_t)__bfloat16_as_ushort(h2) | ((uint32_t)__bfloat16_as_ushort(h3) << 16);
                lp.x = pack2(v0 - __bfloat162float(h0), v1 - __bfloat162float(h1));
                lp.y = pack2(v2 - __bfloat162float(h2), v3 - __bfloat162float(h3));
                *(uint2*)&g_vh[br][b][o][n0 + nc + tx * 4] = hp;
                *(uint2*)&g_vl[br][b][o][n0 + nc + tx * 4] = lp;
            }
        }
    }
}

// ---------------------------------------------------------------------------
// Kernel 2: row stats  c_i = log2( sum_j exp(s_ij) )
// grid (32 i-tiles, 2, 4), block 256 (8 warps), dyn smem 73.7KB
// warp w: S rows 16w..16w+15 of the 128-row tile
// ---------------------------------------------------------------------------
__global__ void __launch_bounds__(256) stats_kernel() {
    extern __shared__ __nv_bfloat16 sm[];
    __nv_bfloat16 *Qh = sm, *Ql = sm + 128 * PIT, *Kh = sm + 2 * 128 * PIT, *Kl = sm + 3 * 128 * PIT;

    int t = threadIdx.x, w = t >> 5, lane = t & 31;
    int i0 = blockIdx.x * 128, br = blockIdx.y, b = blockIdx.z;

    for (int idx = t; idx < 128 * 8; idx += 256) {
        int row = idx >> 3, c8 = idx & 7;
        *(uint4*)&Qh[row * PIT + c8 * 8] = *(const uint4*)&g_qth[br][b][i0 + row][c8 * 8];
        *(uint4*)&Ql[row * PIT + c8 * 8] = *(const uint4*)&g_qtl[br][b][i0 + row][c8 * 8];
    }
    __syncthreads();

    uint32_t aQh[4][4], aQl[4][4];
    {
        uint32_t ah = smem_u32(Qh) + (16 * w + (lane & 15)) * PITB + (lane >> 4) * 16;
        uint32_t al = smem_u32(Ql) + (16 * w + (lane & 15)) * PITB + (lane >> 4) * 16;
        #pragma unroll
        for (int k = 0; k < 4; k++) { ldsm4(aQh[k], ah + k * 32); ldsm4(aQl[k], al + k * 32); }
    }

    uint32_t boff = (lane & 7) * PITB + ((lane >> 3) & 1) * 16;
    uint32_t kh0 = smem_u32(Kh), kl0 = smem_u32(Kl);
    float z0 = 0.f, z1 = 0.f;

    for (int jt = 0; jt < 32; jt++) {
        __syncthreads();
        for (int idx = t; idx < 128 * 8; idx += 256) {
            int row = idx >> 3, c8 = idx & 7;
            *(uint4*)&Kh[row * PIT + c8 * 8] = *(const uint4*)&g_kth[br][b][jt * 128 + row][c8 * 8];
            *(uint4*)&Kl[row * PIT + c8 * 8] = *(const uint4*)&g_ktl[br][b][jt * 128 + row][c8 * 8];
        }
        __syncthreads();

        #pragma unroll
        for (int nt = 0; nt < 16; nt++) {
            float c4[4] = {0.f, 0.f, 0.f, 0.f};
            uint32_t bh = kh0 + nt * 8 * PITB + boff;
            uint32_t bl = kl0 + nt * 8 * PITB + boff;
            #pragma unroll
            for (int k = 0; k < 4; k++) {
                uint32_t bKh[2], bKl[2];
                ldsm2(bKh, bh + k * 32);
                ldsm2(bKl, bl + k * 32);
                mma_bf16(c4, aQh[k], bKh);
                mma_bf16(c4, aQh[k], bKl);
                mma_bf16(c4, aQl[k], bKh);
            }
            z0 += ex2f(c4[0] * L2E) + ex2f(c4[1] * L2E);
            z1 += ex2f(c4[2] * L2E) + ex2f(c4[3] * L2E);
        }
    }

    z0 += __shfl_xor_sync(0xffffffffu, z0, 1);
    z0 += __shfl_xor_sync(0xffffffffu, z0, 2);
    z1 += __shfl_xor_sync(0xffffffffu, z1, 1);
    z1 += __shfl_xor_sync(0xffffffffu, z1, 2);
    if ((lane & 3) == 0) {
        int r0 = i0 + 16 * w + (lane >> 2);
        g_c[br][b][r0]     = __log2f(z0);
        g_c[br][b][r0 + 8] = __log2f(z1);
    }
}

// ---------------------------------------------------------------------------
// Kernel 3: O[c][j] = sum_i v[c][i] * 2^(s[i][j]*L2E - c_i)
// grid (32 j-tiles, 2, 4), block 256, dyn smem 110.6KB
// loop over 64 i-chunks of 64: S'[j][i] mma -> exp epilogue -> P smem -> PV mma
// ---------------------------------------------------------------------------
__global__ void __launch_bounds__(256) pv_kernel() {
    extern __shared__ __nv_bfloat16 sm[];
    __nv_bfloat16 *Kh = sm,                 *Kl = sm + 128 * PIT,
                  *Qh = sm + 2 * 128 * PIT, *Ql = sm + 2 * 128 * PIT + 64 * PIT,
                  *Vh = sm + 3 * 128 * PIT, *Vl = sm + 3 * 128 * PIT + 64 * PIT,
                  *Ph = sm + 4 * 128 * PIT, *Pl = sm + 5 * 128 * PIT;
    __shared__ float cs[64];

    int t = threadIdx.x, w = t >> 5, lane = t & 31;
    int j0 = blockIdx.x * 128, br = blockIdx.y, b = blockIdx.z;

    for (int idx = t; idx < 128 * 8; idx += 256) {
        int row = idx >> 3, c8 = idx & 7;
        *(uint4*)&Kh[row * PIT + c8 * 8] = *(const uint4*)&g_kth[br][b][j0 + row][c8 * 8];
        *(uint4*)&Kl[row * PIT + c8 * 8] = *(const uint4*)&g_ktl[br][b][j0 + row][c8 * 8];
    }
    __syncthreads();

    uint32_t aKh[4][4], aKl[4][4];
    {
        uint32_t ah = smem_u32(Kh) + (16 * w + (lane & 15)) * PITB + (lane >> 4) * 16;
        uint32_t al = smem_u32(Kl) + (16 * w + (lane & 15)) * PITB + (lane >> 4) * 16;
        #pragma unroll
        for (int k = 0; k < 4; k++) { ldsm4(aKh[k], ah + k * 32); ldsm4(aKl[k], al + k * 32); }
    }

    uint32_t boff = (lane & 7) * PITB + ((lane >> 3) & 1) * 16;
    uint32_t qh0 = smem_u32(Qh), ql0 = smem_u32(Ql);
    uint32_t ph0 = smem_u32(Ph), pl0 = smem_u32(Pl);
    uint32_t vh0 = smem_u32(Vh), vl0 = smem_u32(Vl);

    float oacc[4][2][4] = {};

    for (int it = 0; it < 64; it++) {
        int i0 = it * 64;
        __syncthreads();
        for (int idx = t; idx < 64 * 8; idx += 256) {
            int row = idx >> 3, c8 = idx & 7;
            *(uint4*)&Qh[row * PIT + c8 * 8] = *(const uint4*)&g_qth[br][b][i0 + row][c8 * 8];
            *(uint4*)&Ql[row * PIT + c8 * 8] = *(const uint4*)&g_qtl[br][b][i0 + row][c8 * 8];
            *(uint4*)&Vh[row * PIT + c8 * 8] = *(const uint4*)&g_vh[br][b][row][i0 + c8 * 8];
            *(uint4*)&Vl[row * PIT + c8 * 8] = *(const uint4*)&g_vl[br][b][row][i0 + c8 * 8];
        }
        if (t < 64) cs[t] = g_c[br][b][i0 + t];
        __syncthreads();

        // S'[j][i]: warp w -> rows 16w..16w+15, cols 0..63 (8 n-tiles)
        #pragma unroll
        for (int nt = 0; nt < 8; nt++) {
            float c4[4] = {0.f, 0.f, 0.f, 0.f};
            uint32_t bh = qh0 + nt * 8 * PITB + boff;
            uint32_t bl = ql0 + nt * 8 * PITB + boff;
            #pragma unroll
            for (int k = 0; k < 4; k++) {
                uint32_t bQh[2], bQl[2];
                ldsm2(bQh, bh + k * 32);
                ldsm2(bQl, bl + k * 32);
                mma_bf16(c4, aKh[k], bQh);
                mma_bf16(c4, aKh[k], bQl);
                mma_bf16(c4, aKl[k], bQh);
            }
            int col = nt * 8 + 2 * (lane & 3);
            float2 cc = *(float2*)&cs[col];
            int jr = 16 * w + (lane >> 2);
            float p0 = ex2f(fmaf(c4[0], L2E, -cc.x));
            float p1 = ex2f(fmaf(c4[1], L2E, -cc.y));
            float p2 = ex2f(fmaf(c4[2], L2E, -cc.x));
            float p3 = ex2f(fmaf(c4[3], L2E, -cc.y));
            __nv_bfloat16 h0 = __float2bfloat16(p0), h1 = __float2bfloat16(p1);
            __nv_bfloat16 h2 = __float2bfloat16(p2), h3 = __float2bfloat16(p3);
            *(uint32_t*)&Ph[jr * PIT + col] =
                (uint32_t)__bfloat16_as_ushort(h0) | ((uint32_t)__bfloat16_as_ushort(h1) << 16);
            *(uint32_t*)&Ph[(jr + 8) * PIT + col] =
                (uint32_t)__bfloat16_as_ushort(h2) | ((uint32_t)__bfloat16_as_ushort(h3) << 16);
            *(uint32_t*)&Pl[jr * PIT + col] =
                pack2(p0 - __bfloat162float(h0), p1 - __bfloat162float(h1));
            *(uint32_t*)&Pl[(jr + 8) * PIT + col] =
                pack2(p2 - __bfloat162float(h2), p3 - __bfloat162float(h3));
        }
        __syncthreads();

        // O[c][j] += V[c][i] * P[j][i]:  warp w -> cols j 16w..16w+15 (2 n-tiles), rows c 0..63 (4 m-tiles)
        #pragma unroll
        for (int mt = 0; mt < 4; mt++) {
            uint32_t avh[4][4], avl[4][4];
            uint32_t ah = vh0 + (16 * mt + (lane & 15)) * PITB + (lane >> 4) * 16;
            uint32_t al = vl0 + (16 * mt + (lane & 15)) * PITB + (lane >> 4) * 16;
            #pragma unroll
            for (int k = 0; k < 4; k++) { ldsm4(avh[k], ah + k * 32); ldsm4(avl[k], al + k * 32); }
            #pragma unroll
            for (int nt2 = 0; nt2 < 2; nt2++) {
                uint32_t bh = ph0 + (16 * w + 8 * nt2) * PITB + boff;
                uint32_t bl = pl0 + (16 * w + 8 * nt2) * PITB + boff;
                #pragma unroll
                for (int k = 0; k < 4; k++) {
                    uint32_t bP[2], bPl[2];
                    ldsm2(bP,  bh + k * 32);
                    ldsm2(bPl, bl + k * 32);
                    mma_bf16(oacc[mt][nt2], avh[k], bP);
                    mma_bf16(oacc[mt][nt2], avh[k], bPl);
                    mma_bf16(oacc[mt][nt2], avl[k], bP);
                }
            }
        }
    }

    #pragma unroll
    for (int mt = 0; mt < 4; mt++)
        #pragma unroll
        for (int nt2 = 0; nt2 < 2; nt2++) {
            int c0 = 16 * mt + (lane >> 2);
            int jc = j0 + 16 * w + 8 * nt2 + 2 * (lane & 3);
            *(float2*)&g_o[br][b][c0][jc]     = make_float2(oacc[mt][nt2][0], oacc[mt][nt2][1]);
            *(float2*)&g_o[br][b][c0 + 8][jc] = make_float2(oacc[mt][nt2][2], oacc[mt][nt2][3]);
        }
}

// ---------------------------------------------------------------------------
// Kernel 4: final fuse conv
// ---------------------------------------------------------------------------
__global__ void __launch_bounds__(256) final_kernel(const float* __restrict__ Wf,
                             const float* __restrict__ bf,
                             const float* __restrict__ g1p,
                             const float* __restrict__ g2p,
                             float* __restrict__ y) {
    extern __shared__ float smf[];
    float (*Wt)[64] = (float(*)[64])smf;
    float (*csm)[64] = (float(*)[64])(smf + 128 * 64);
    float* bs = smf + 2 * 128 * 64;

    int t = threadIdx.x;
    int b = blockIdx.y;
    int n0 = blockIdx.x * 512;
    float gg1 = *g1p, gg2 = *g2p;

    for (int idx = t; idx < 64 * 128; idx += 256) {
        int o = idx >> 7, c = idx & 127;
        Wt[c][o] = Wf[idx];
    }
    if (t < 64) bs[t] = bf[t];
    __syncthreads();

    int tx = t & 15, ty = t >> 4;
    for (int nc = 0; nc < 512; nc += 64) {
        __syncthreads();
        for (int idx = t; idx < 128 * 16; idx += 256) {
            int c = idx >> 4, n4 = idx & 15;
            const float* src = (c < 64) ? &g_o[0][b][c][0] : &g_o[1][b][c - 64][0];
            float g = (c < 64) ? gg1 : gg2;
            float4 v4 = *(const float4*)&src[n0 + nc + n4 * 4];
            v4.x *= g; v4.y *= g; v4.z *= g; v4.w *= g;
            *(float4*)&csm[c][n4 * 4] = v4;
        }
        __syncthreads();

        float acc[4][4] = {};
        #pragma unroll 8
        for (int c = 0; c < 128; c++) {
            float wv[4], xv[4];
            *(float4*)wv = *(float4*)&Wt[c][ty * 4];
            *(float4*)xv = *(float4*)&csm[c][tx * 4];
            #pragma unroll
            for (int i = 0; i < 4; i++)
                #pragma unroll
                for (int j = 0; j < 4; j++)
                    acc[i][j] += wv[i] * xv[j];
        }
        #pragma unroll
        for (int i = 0; i < 4; i++) {
            int o = ty * 4 + i;
            float bb = bs[o];
            float4 r = make_float4(acc[i][0] + bb, acc[i][1] + bb,
                                   acc[i][2] + bb, acc[i][3] + bb);
            *(float4*)&y[(size_t)b * 64 * NTOK + o * NTOK + n0 + nc + tx * 4] = r;
        }
    }
}

// ---------------------------------------------------------------------------
extern "C" void kernel_launch(void* const* d_in, const int* in_sizes, int n_in,
                              void* d_out, int out_size) {
    const float* x  = (const float*)d_in[0];
    const float* g1 = (const float*)d_in[13];
    const float* g2 = (const float*)d_in[14];
    const float* Wf = (const float*)d_in[15];
    const float* bf = (const float*)d_in[16];
    float* y = (float*)d_out;

    ProjArgs pa;
    for (int mi = 0; mi < 6; mi++) {
        pa.W[mi] = (const float*)d_in[1 + 2 * mi];
        pa.B[mi] = (const float*)d_in[2 + 2 * mi];
    }

    const int smP = (4096 + 4096 + 64) * 4 + 2 * 64 * PIT * 2;   // 51456
    const int smS = 4 * 128 * PIT * 2;                           // 73728
    const int smV = 6 * 128 * PIT * 2;                           // 110592
    const int smF = (2 * 128 * 64 + 64) * 4;                     // 65792

    cudaFuncSetAttribute(proj_kernel,  cudaFuncAttributeMaxDynamicSharedMemorySize, smP);
    cudaFuncSetAttribute(stats_kernel, cudaFuncAttributeMaxDynamicSharedMemorySize, smS);
    cudaFuncSetAttribute(pv_kernel,    cudaFuncAttributeMaxDynamicSharedMemorySize, smV);
    cudaFuncSetAttribute(final_kernel, cudaFuncAttributeMaxDynamicSharedMemorySize, smF);

    proj_kernel<<<dim3(8, 4, 6), 256, smP>>>(x, pa);
    stats_kernel<<<dim3(32, 2, 4), 256, smS>>>();
    pv_kernel<<<dim3(32, 2, 4), 256, smV>>>();
    final_kernel<<<dim3(8, 4), 256, smF>>>(Wf, bf, g1, g2, y);
}

// round 5
// speedup vs baseline: 3.1726x; 1.1062x over previous
#include <cuda_runtime.h>
#include <cuda_bf16.h>
#include <cstdint>

#define NTOK 4096
#define L2E  1.4426950408889634f
#define PIT  72          // smem pitch in bf16 elements
#define PITB 144         // smem pitch in bytes

// ---------------- scratch ----------------
__device__ __nv_bfloat16 g_qth[2][4][NTOK][64];
__device__ __nv_bfloat16 g_qtl[2][4][NTOK][64];
__device__ __nv_bfloat16 g_kth[2][4][NTOK][64];
__device__ __nv_bfloat16 g_ktl[2][4][NTOK][64];
__device__ __nv_bfloat16 g_vh [2][4][64][NTOK];
__device__ __nv_bfloat16 g_vl [2][4][64][NTOK];
__device__ float g_c[2][4][NTOK];
__device__ float g_o[2][4][64][NTOK];

// ---------------- helpers ----------------
__device__ __forceinline__ uint32_t smem_u32(const void* p) {
    uint32_t a;
    asm("{ .reg .u64 t; cvta.to.shared.u64 t, %1; cvt.u32.u64 %0, t; }" : "=r"(a) : "l"(p));
    return a;
}
__device__ __forceinline__ float ex2f(float x) {
    float r; asm("ex2.approx.ftz.f32 %0, %1;" : "=f"(r) : "f"(x)); return r;
}
__device__ __forceinline__ void ldsm4(uint32_t* r, uint32_t a) {
    asm volatile("ldmatrix.sync.aligned.m8n8.x4.shared.b16 {%0,%1,%2,%3}, [%4];"
                 : "=r"(r[0]), "=r"(r[1]), "=r"(r[2]), "=r"(r[3]) : "r"(a));
}
__device__ __forceinline__ void ldsm2(uint32_t* r, uint32_t a) {
    asm volatile("ldmatrix.sync.aligned.m8n8.x2.shared.b16 {%0,%1}, [%2];"
                 : "=r"(r[0]), "=r"(r[1]) : "r"(a));
}
__device__ __forceinline__ void mma_bf16(float* c, const uint32_t* a, const uint32_t* b) {
    asm volatile("mma.sync.aligned.m16n8k16.row.col.f32.bf16.bf16.f32 "
                 "{%0,%1,%2,%3}, {%4,%5,%6,%7}, {%8,%9}, {%0,%1,%2,%3};"
                 : "+f"(c[0]), "+f"(c[1]), "+f"(c[2]), "+f"(c[3])
                 : "r"(a[0]), "r"(a[1]), "r"(a[2]), "r"(a[3]), "r"(b[0]), "r"(b[1]));
}
__device__ __forceinline__ uint32_t pack2(float a, float b) {
    __nv_bfloat16 ha = __float2bfloat16(a), hb = __float2bfloat16(b);
    return (uint32_t)__bfloat16_as_ushort(ha) | ((uint32_t)__bfloat16_as_ushort(hb) << 16);
}

// ---------------------------------------------------------------------------
// Kernel 1: fused projections -> bf16 hi/lo in MMA-ready (k-contiguous) layouts
// grid (16 n-splits, 4 batches, 6 mats), block 256, dyn smem ~50.3KB
// ---------------------------------------------------------------------------
struct ProjArgs { const float* W[6]; const float* B[6]; };

__global__ void __launch_bounds__(256, 2) proj_kernel(const float* __restrict__ x, ProjArgs pa) {
    extern __shared__ char dsm[];
    float* Wt = (float*)dsm;                 // [64][64] Wt[c][o]
    float* xs = Wt + 4096;                   // [64][64] xs[c][n]
    float* bs = xs + 4096;                   // [64]
    __nv_bfloat16* tsh = (__nv_bfloat16*)(bs + 64);  // [64][PIT]
    __nv_bfloat16* tsl = tsh + 64 * PIT;

    int t = threadIdx.x;
    int b = blockIdx.y;
    int n0 = blockIdx.x * 256;
    int z = blockIdx.z, br = z / 3, which = z % 3;
    const float* W = pa.W[z];
    const float* bias = pa.B[z];

    for (int idx = t; idx < 64 * 64; idx += 256) {
        int o = idx >> 6, c = idx & 63;
        Wt[c * 64 + o] = W[idx];
    }
    if (t < 64) bs[t] = bias[t];
    __syncthreads();

    const float* xb = x + (size_t)b * 64 * NTOK;
    int tx = t & 15, ty = t >> 4;

    __nv_bfloat16 (*th)[64] = (which == 0) ? g_qth[br][b] : g_kth[br][b];
    __nv_bfloat16 (*tl)[64] = (which == 0) ? g_qtl[br][b] : g_ktl[br][b];

    for (int nc = 0; nc < 256; nc += 64) {
        __syncthreads();
        for (int idx = t; idx < 64 * 16; idx += 256) {
            int c = idx >> 4, n4 = idx & 15;
            *(float4*)&xs[c * 64 + n4 * 4] = *(const float4*)&xb[c * NTOK + n0 + nc + n4 * 4];
        }
        __syncthreads();

        float acc[4][4] = {};
        #pragma unroll 8
        for (int c = 0; c < 64; c++) {
            float wv[4], xv[4];
            *(float4*)wv = *(float4*)&Wt[c * 64 + ty * 4];
            *(float4*)xv = *(float4*)&xs[c * 64 + tx * 4];
            #pragma unroll
            for (int i = 0; i < 4; i++)
                #pragma unroll
                for (int j = 0; j < 4; j++)
                    acc[i][j] += wv[i] * xv[j];
        }

        if (which < 2) {
            // transpose via smem, then coalesced 16B stores
            #pragma unroll
            for (int j = 0; j < 4; j++) {
                int nl = tx * 4 + j;
                #pragma unroll
                for (int i = 0; i < 4; i++) {
                    int o = ty * 4 + i;
                    float v = acc[i][j] + bs[o];
                    __nv_bfloat16 h = __float2bfloat16(v);
                    tsh[nl * PIT + o] = h;
                    tsl[nl * PIT + o] = __float2bfloat16(v - __bfloat162float(h));
                }
            }
            __syncthreads();
            for (int idx = t; idx < 64 * 8; idx += 256) {
                int row = idx >> 3, c8 = idx & 7;
                *(uint4*)&th[n0 + nc + row][c8 * 8] = *(uint4*)&tsh[row * PIT + c8 * 8];
                *(uint4*)&tl[n0 + nc + row][c8 * 8] = *(uint4*)&tsl[row * PIT + c8 * 8];
            }
        } else {
            #pragma unroll
            for (int i = 0; i < 4; i++) {
                int o = ty * 4 + i;
                float bb = bs[o];
                float v0 = acc[i][0] + bb, v1 = acc[i][1] + bb;
                float v2 = acc[i][2] + bb, v3 = acc[i][3] + bb;
                __nv_bfloat16 h0 = __float2bfloat16(v0), h1 = __float2bfloat16(v1);
                __nv_bfloat16 h2 = __float2bfloat16(v2), h3 = __float2bfloat16(v3);
                uint2 hp, lp;
                hp.x = (uint32_t)__bfloat16_as_ushort(h0) | ((uint32_t)__bfloat16_as_ushort(h1) << 16);
                hp.y = (uint32_t)__bfloat16_as_ushort(h2) | ((uint32_t)__bfloat16_as_ushort(h3) << 16);
                lp.x = pack2(v0 - __bfloat162float(h0), v1 - __bfloat162float(h1));
                lp.y = pack2(v2 - __bfloat162float(h2), v3 - __bfloat162float(h3));
                *(uint2*)&g_vh[br][b][o][n0 + nc + tx * 4] = hp;
                *(uint2*)&g_vl[br][b][o][n0 + nc + tx * 4] = lp;
            }
        }
    }
}

// ---------------------------------------------------------------------------
// Kernel 2: row stats  c_i = log2( sum_j exp(s_ij) )
// grid (32 i-tiles, 2, 4), block 256 (8 warps), dyn smem 73.7KB, 2 CTA/SM
// ---------------------------------------------------------------------------
__global__ void __launch_bounds__(256, 2) stats_kernel() {
    extern __shared__ __nv_bfloat16 sm[];
    __nv_bfloat16 *Qh = sm, *Ql = sm + 128 * PIT, *Kh = sm + 2 * 128 * PIT, *Kl = sm + 3 * 128 * PIT;

    int t = threadIdx.x, w = t >> 5, lane = t & 31;
    int i0 = blockIdx.x * 128, br = blockIdx.y, b = blockIdx.z;

    for (int idx = t; idx < 128 * 8; idx += 256) {
        int row = idx >> 3, c8 = idx & 7;
        *(uint4*)&Qh[row * PIT + c8 * 8] = *(const uint4*)&g_qth[br][b][i0 + row][c8 * 8];
        *(uint4*)&Ql[row * PIT + c8 * 8] = *(const uint4*)&g_qtl[br][b][i0 + row][c8 * 8];
    }
    __syncthreads();

    uint32_t aQh[4][4], aQl[4][4];
    {
        uint32_t ah = smem_u32(Qh) + (16 * w + (lane & 15)) * PITB + (lane >> 4) * 16;
        uint32_t al = smem_u32(Ql) + (16 * w + (lane & 15)) * PITB + (lane >> 4) * 16;
        #pragma unroll
        for (int k = 0; k < 4; k++) { ldsm4(aQh[k], ah + k * 32); ldsm4(aQl[k], al + k * 32); }
    }

    uint32_t boff = (lane & 7) * PITB + ((lane >> 3) & 1) * 16;
    uint32_t kh0 = smem_u32(Kh), kl0 = smem_u32(Kl);
    float z0 = 0.f, z1 = 0.f;

    for (int jt = 0; jt < 32; jt++) {
        __syncthreads();
        for (int idx = t; idx < 128 * 8; idx += 256) {
            int row = idx >> 3, c8 = idx & 7;
            *(uint4*)&Kh[row * PIT + c8 * 8] = *(const uint4*)&g_kth[br][b][jt * 128 + row][c8 * 8];
            *(uint4*)&Kl[row * PIT + c8 * 8] = *(const uint4*)&g_ktl[br][b][jt * 128 + row][c8 * 8];
        }
        __syncthreads();

        #pragma unroll
        for (int nt = 0; nt < 16; nt++) {
            float c4[4] = {0.f, 0.f, 0.f, 0.f};
            uint32_t bh = kh0 + nt * 8 * PITB + boff;
            uint32_t bl = kl0 + nt * 8 * PITB + boff;
            #pragma unroll
            for (int k = 0; k < 4; k++) {
                uint32_t bKh[2], bKl[2];
                ldsm2(bKh, bh + k * 32);
                ldsm2(bKl, bl + k * 32);
                mma_bf16(c4, aQh[k], bKh);
                mma_bf16(c4, aQh[k], bKl);
                mma_bf16(c4, aQl[k], bKh);
            }
            z0 += ex2f(c4[0] * L2E) + ex2f(c4[1] * L2E);
            z1 += ex2f(c4[2] * L2E) + ex2f(c4[3] * L2E);
        }
    }

    z0 += __shfl_xor_sync(0xffffffffu, z0, 1);
    z0 += __shfl_xor_sync(0xffffffffu, z0, 2);
    z1 += __shfl_xor_sync(0xffffffffu, z1, 1);
    z1 += __shfl_xor_sync(0xffffffffu, z1, 2);
    if ((lane & 3) == 0) {
        int r0 = i0 + 16 * w + (lane >> 2);
        g_c[br][b][r0]     = __log2f(z0);
        g_c[br][b][r0 + 8] = __log2f(z1);
    }
}

// ---------------------------------------------------------------------------
// Kernel 3: O[c][j] = sum_i v[c][i] * 2^(s[i][j]*L2E - c_i)
// grid (32 j-tiles, 2, 4), block 256, dyn smem 110.6KB, 2 CTA/SM target
// ---------------------------------------------------------------------------
__global__ void __launch_bounds__(256, 2) pv_kernel() {
    extern __shared__ __nv_bfloat16 sm[];
    __nv_bfloat16 *Kh = sm,                 *Kl = sm + 128 * PIT,
                  *Qh = sm + 2 * 128 * PIT, *Ql = sm + 2 * 128 * PIT + 64 * PIT,
                  *Vh = sm + 3 * 128 * PIT, *Vl = sm + 3 * 128 * PIT + 64 * PIT,
                  *Ph = sm + 4 * 128 * PIT, *Pl = sm + 5 * 128 * PIT;
    __shared__ float cs[64];

    int t = threadIdx.x, w = t >> 5, lane = t & 31;
    int j0 = blockIdx.x * 128, br = blockIdx.y, b = blockIdx.z;

    for (int idx = t; idx < 128 * 8; idx += 256) {
        int row = idx >> 3, c8 = idx & 7;
        *(uint4*)&Kh[row * PIT + c8 * 8] = *(const uint4*)&g_kth[br][b][j0 + row][c8 * 8];
        *(uint4*)&Kl[row * PIT + c8 * 8] = *(const uint4*)&g_ktl[br][b][j0 + row][c8 * 8];
    }
    __syncthreads();

    uint32_t aKh[4][4], aKl[4][4];
    {
        uint32_t ah = smem_u32(Kh) + (16 * w + (lane & 15)) * PITB + (lane >> 4) * 16;
        uint32_t al = smem_u32(Kl) + (16 * w + (lane & 15)) * PITB + (lane >> 4) * 16;
        #pragma unroll
        for (int k = 0; k < 4; k++) { ldsm4(aKh[k], ah + k * 32); ldsm4(aKl[k], al + k * 32); }
    }

    uint32_t boff = (lane & 7) * PITB + ((lane >> 3) & 1) * 16;
    uint32_t qh0 = smem_u32(Qh), ql0 = smem_u32(Ql);
    uint32_t ph0 = smem_u32(Ph), pl0 = smem_u32(Pl);
    uint32_t vh0 = smem_u32(Vh), vl0 = smem_u32(Vl);

    float oacc[4][2][4] = {};

    for (int it = 0; it < 64; it++) {
        int i0 = it * 64;
        __syncthreads();
        for (int idx = t; idx < 64 * 8; idx += 256) {
            int row = idx >> 3, c8 = idx & 7;
            *(uint4*)&Qh[row * PIT + c8 * 8] = *(const uint4*)&g_qth[br][b][i0 + row][c8 * 8];
            *(uint4*)&Ql[row * PIT + c8 * 8] = *(const uint4*)&g_qtl[br][b][i0 + row][c8 * 8];
            *(uint4*)&Vh[row * PIT + c8 * 8] = *(const uint4*)&g_vh[br][b][row][i0 + c8 * 8];
            *(uint4*)&Vl[row * PIT + c8 * 8] = *(const uint4*)&g_vl[br][b][row][i0 + c8 * 8];
        }
        if (t < 64) cs[t] = g_c[br][b][i0 + t];
        __syncthreads();

        // S'[j][i]: warp w -> rows 16w..16w+15, cols 0..63 (8 n-tiles)
        #pragma unroll
        for (int nt = 0; nt < 8; nt++) {
            float c4[4] = {0.f, 0.f, 0.f, 0.f};
            uint32_t bh = qh0 + nt * 8 * PITB + boff;
            uint32_t bl = ql0 + nt * 8 * PITB + boff;
            #pragma unroll
            for (int k = 0; k < 4; k++) {
                uint32_t bQh[2], bQl[2];
                ldsm2(bQh, bh + k * 32);
                ldsm2(bQl, bl + k * 32);
                mma_bf16(c4, aKh[k], bQh);
                mma_bf16(c4, aKh[k], bQl);
                mma_bf16(c4, aKl[k], bQh);
            }
            int col = nt * 8 + 2 * (lane & 3);
            float2 cc = *(float2*)&cs[col];
            int jr = 16 * w + (lane >> 2);
            float p0 = ex2f(fmaf(c4[0], L2E, -cc.x));
            float p1 = ex2f(fmaf(c4[1], L2E, -cc.y));
            float p2 = ex2f(fmaf(c4[2], L2E, -cc.x));
            float p3 = ex2f(fmaf(c4[3], L2E, -cc.y));
            __nv_bfloat16 h0 = __float2bfloat16(p0), h1 = __float2bfloat16(p1);
            __nv_bfloat16 h2 = __float2bfloat16(p2), h3 = __float2bfloat16(p3);
            *(uint32_t*)&Ph[jr * PIT + col] =
                (uint32_t)__bfloat16_as_ushort(h0) | ((uint32_t)__bfloat16_as_ushort(h1) << 16);
            *(uint32_t*)&Ph[(jr + 8) * PIT + col] =
                (uint32_t)__bfloat16_as_ushort(h2) | ((uint32_t)__bfloat16_as_ushort(h3) << 16);
            *(uint32_t*)&Pl[jr * PIT + col] =
                pack2(p0 - __bfloat162float(h0), p1 - __bfloat162float(h1));
            *(uint32_t*)&Pl[(jr + 8) * PIT + col] =
                pack2(p2 - __bfloat162float(h2), p3 - __bfloat162float(h3));
        }
        __syncthreads();

        // O[c][j] += V[c][i] * P[j][i]
        #pragma unroll
        for (int mt = 0; mt < 4; mt++) {
            uint32_t avh[4][4], avl[4][4];
            uint32_t ah = vh0 + (16 * mt + (lane & 15)) * PITB + (lane >> 4) * 16;
            uint32_t al = vl0 + (16 * mt + (lane & 15)) * PITB + (lane >> 4) * 16;
            #pragma unroll
            for (int k = 0; k < 4; k++) { ldsm4(avh[k], ah + k * 32); ldsm4(avl[k], al + k * 32); }
            #pragma unroll
            for (int nt2 = 0; nt2 < 2; nt2++) {
                uint32_t bh = ph0 + (16 * w + 8 * nt2) * PITB + boff;
                uint32_t bl = pl0 + (16 * w + 8 * nt2) * PITB + boff;
                #pragma unroll
                for (int k = 0; k < 4; k++) {
                    uint32_t bP[2], bPl[2];
                    ldsm2(bP,  bh + k * 32);
                    ldsm2(bPl, bl + k * 32);
                    mma_bf16(oacc[mt][nt2], avh[k], bP);
                    mma_bf16(oacc[mt][nt2], avh[k], bPl);
                    mma_bf16(oacc[mt][nt2], avl[k], bP);
                }
            }
        }
    }

    #pragma unroll
    for (int mt = 0; mt < 4; mt++)
        #pragma unroll
        for (int nt2 = 0; nt2 < 2; nt2++) {
            int c0 = 16 * mt + (lane >> 2);
            int jc = j0 + 16 * w + 8 * nt2 + 2 * (lane & 3);
            *(float2*)&g_o[br][b][c0][jc]     = make_float2(oacc[mt][nt2][0], oacc[mt][nt2][1]);
            *(float2*)&g_o[br][b][c0 + 8][jc] = make_float2(oacc[mt][nt2][2], oacc[mt][nt2][3]);
        }
}

// ---------------------------------------------------------------------------
// Kernel 4: final fuse conv  grid (32, 4), 128-token chunks
// ---------------------------------------------------------------------------
__global__ void __launch_bounds__(256, 2) final_kernel(const float* __restrict__ Wf,
                             const float* __restrict__ bf,
                             const float* __restrict__ g1p,
                             const float* __restrict__ g2p,
                             float* __restrict__ y) {
    extern __shared__ float smf[];
    float (*Wt)[64] = (float(*)[64])smf;
    float (*csm)[64] = (float(*)[64])(smf + 128 * 64);
    float* bs = smf + 2 * 128 * 64;

    int t = threadIdx.x;
    int b = blockIdx.y;
    int n0 = blockIdx.x * 128;
    float gg1 = *g1p, gg2 = *g2p;

    for (int idx = t; idx < 64 * 128; idx += 256) {
        int o = idx >> 7, c = idx & 127;
        Wt[c][o] = Wf[idx];
    }
    if (t < 64) bs[t] = bf[t];
    __syncthreads();

    int tx = t & 15, ty = t >> 4;
    for (int nc = 0; nc < 128; nc += 64) {
        __syncthreads();
        for (int idx = t; idx < 128 * 16; idx += 256) {
            int c = idx >> 4, n4 = idx & 15;
            const float* src = (c < 64) ? &g_o[0][b][c][0] : &g_o[1][b][c - 64][0];
            float g = (c < 64) ? gg1 : gg2;
            float4 v4 = *(const float4*)&src[n0 + nc + n4 * 4];
            v4.x *= g; v4.y *= g; v4.z *= g; v4.w *= g;
            *(float4*)&csm[c][n4 * 4] = v4;
        }
        __syncthreads();

        float acc[4][4] = {};
        #pragma unroll 8
        for (int c = 0; c < 128; c++) {
            float wv[4], xv[4];
            *(float4*)wv = *(float4*)&Wt[c][ty * 4];
            *(float4*)xv = *(float4*)&csm[c][tx * 4];
            #pragma unroll
            for (int i = 0; i < 4; i++)
                #pragma unroll
                for (int j = 0; j < 4; j++)
                    acc[i][j] += wv[i] * xv[j];
        }
        #pragma unroll
        for (int i = 0; i < 4; i++) {
            int o = ty * 4 + i;
            float bb = bs[o];
            float4 r = make_float4(acc[i][0] + bb, acc[i][1] + bb,
                                   acc[i][2] + bb, acc[i][3] + bb);
            *(float4*)&y[(size_t)b * 64 * NTOK + o * NTOK + n0 + nc + tx * 4] = r;
        }
    }
}

// ---------------------------------------------------------------------------
extern "C" void kernel_launch(void* const* d_in, const int* in_sizes, int n_in,
                              void* d_out, int out_size) {
    const float* x  = (const float*)d_in[0];
    const float* g1 = (const float*)d_in[13];
    const float* g2 = (const float*)d_in[14];
    const float* Wf = (const float*)d_in[15];
    const float* bf = (const float*)d_in[16];
    float* y = (float*)d_out;

    ProjArgs pa;
    for (int mi = 0; mi < 6; mi++) {
        pa.W[mi] = (const float*)d_in[1 + 2 * mi];
        pa.B[mi] = (const float*)d_in[2 + 2 * mi];
    }

    const int smP = (4096 + 4096 + 64) * 4 + 2 * 64 * PIT * 2;   // 51456
    const int smS = 4 * 128 * PIT * 2;                           // 73728
    const int smV = 6 * 128 * PIT * 2;                           // 110592
    const int smF = (2 * 128 * 64 + 64) * 4;                     // 65792

    cudaFuncSetAttribute(proj_kernel,  cudaFuncAttributeMaxDynamicSharedMemorySize, smP);
    cudaFuncSetAttribute(stats_kernel, cudaFuncAttributeMaxDynamicSharedMemorySize, smS);
    cudaFuncSetAttribute(pv_kernel,    cudaFuncAttributeMaxDynamicSharedMemorySize, smV);
    cudaFuncSetAttribute(final_kernel, cudaFuncAttributeMaxDynamicSharedMemorySize, smF);

    proj_kernel<<<dim3(16, 4, 6), 256, smP>>>(x, pa);
    stats_kernel<<<dim3(32, 2, 4), 256, smS>>>();
    pv_kernel<<<dim3(32, 2, 4), 256, smV>>>();
    final_kernel<<<dim3(32, 4), 256, smF>>>(Wf, bf, g1, g2, y);
}

// round 6
// speedup vs baseline: 3.3551x; 1.0575x over previous
#include <cuda_runtime.h>
#include <cuda_bf16.h>
#include <cstdint>

#define NTOK 4096
#define L2E  1.4426950408889634f
#define PIT  72          // smem pitch in bf16 elements
#define PITB 144         // smem pitch in bytes
#define REG  36864       // region size: 128 rows * 144B * 2 (hi+lo)

// ---------------- scratch ----------------
__device__ __nv_bfloat16 g_qth[2][4][NTOK][64];
__device__ __nv_bfloat16 g_qtl[2][4][NTOK][64];
__device__ __nv_bfloat16 g_kth[2][4][NTOK][64];
__device__ __nv_bfloat16 g_ktl[2][4][NTOK][64];
__device__ __nv_bfloat16 g_vh [2][4][64][NTOK];
__device__ __nv_bfloat16 g_vl [2][4][64][NTOK];
__device__ float g_c[2][4][NTOK];
__device__ float g_o[2][4][64][NTOK];

// ---------------- helpers ----------------
__device__ __forceinline__ uint32_t smem_u32(const void* p) {
    uint32_t a;
    asm("{ .reg .u64 t; cvta.to.shared.u64 t, %1; cvt.u32.u64 %0, t; }" : "=r"(a) : "l"(p));
    return a;
}
__device__ __forceinline__ float ex2f(float x) {
    float r; asm("ex2.approx.ftz.f32 %0, %1;" : "=f"(r) : "f"(x)); return r;
}
__device__ __forceinline__ void ldsm4(uint32_t* r, uint32_t a) {
    asm volatile("ldmatrix.sync.aligned.m8n8.x4.shared.b16 {%0,%1,%2,%3}, [%4];"
                 : "=r"(r[0]), "=r"(r[1]), "=r"(r[2]), "=r"(r[3]) : "r"(a));
}
__device__ __forceinline__ void ldsm2(uint32_t* r, uint32_t a) {
    asm volatile("ldmatrix.sync.aligned.m8n8.x2.shared.b16 {%0,%1}, [%2];"
                 : "=r"(r[0]), "=r"(r[1]) : "r"(a));
}
__device__ __forceinline__ void mma_bf16(float* c, const uint32_t* a, const uint32_t* b) {
    asm volatile("mma.sync.aligned.m16n8k16.row.col.f32.bf16.bf16.f32 "
                 "{%0,%1,%2,%3}, {%4,%5,%6,%7}, {%8,%9}, {%0,%1,%2,%3};"
                 : "+f"(c[0]), "+f"(c[1]), "+f"(c[2]), "+f"(c[3])
                 : "r"(a[0]), "r"(a[1]), "r"(a[2]), "r"(a[3]), "r"(b[0]), "r"(b[1]));
}
__device__ __forceinline__ uint32_t pack2(float a, float b) {
    __nv_bfloat16 ha = __float2bfloat16(a), hb = __float2bfloat16(b);
    return (uint32_t)__bfloat16_as_ushort(ha) | ((uint32_t)__bfloat16_as_ushort(hb) << 16);
}
__device__ __forceinline__ void cp16(uint32_t d, const void* s) {
    asm volatile("cp.async.cg.shared.global [%0], [%1], 16;" :: "r"(d), "l"(s));
}
#define CP_COMMIT() asm volatile("cp.async.commit_group;" ::: "memory")
#define CP_WAIT0()  asm volatile("cp.async.wait_group 0;" ::: "memory")
#define CP_WAIT1()  asm volatile("cp.async.wait_group 1;" ::: "memory")

// ---------------------------------------------------------------------------
// Kernel 1: fused projections -> bf16 hi/lo in MMA-ready (k-contiguous) layouts
// ---------------------------------------------------------------------------
struct ProjArgs { const float* W[6]; const float* B[6]; };

__global__ void __launch_bounds__(256, 2) proj_kernel(const float* __restrict__ x, ProjArgs pa) {
    extern __shared__ char dsm[];
    float* Wt = (float*)dsm;
    float* xs = Wt + 4096;
    float* bs = xs + 4096;
    __nv_bfloat16* tsh = (__nv_bfloat16*)(bs + 64);
    __nv_bfloat16* tsl = tsh + 64 * PIT;

    int t = threadIdx.x;
    int b = blockIdx.y;
    int n0 = blockIdx.x * 256;
    int z = blockIdx.z, br = z / 3, which = z % 3;
    const float* W = pa.W[z];
    const float* bias = pa.B[z];

    for (int idx = t; idx < 64 * 64; idx += 256) {
        int o = idx >> 6, c = idx & 63;
        Wt[c * 64 + o] = W[idx];
    }
    if (t < 64) bs[t] = bias[t];
    __syncthreads();

    const float* xb = x + (size_t)b * 64 * NTOK;
    int tx = t & 15, ty = t >> 4;

    __nv_bfloat16 (*th)[64] = (which == 0) ? g_qth[br][b] : g_kth[br][b];
    __nv_bfloat16 (*tl)[64] = (which == 0) ? g_qtl[br][b] : g_ktl[br][b];

    for (int nc = 0; nc < 256; nc += 64) {
        __syncthreads();
        for (int idx = t; idx < 64 * 16; idx += 256) {
            int c = idx >> 4, n4 = idx & 15;
            *(float4*)&xs[c * 64 + n4 * 4] = *(const float4*)&xb[c * NTOK + n0 + nc + n4 * 4];
        }
        __syncthreads();

        float acc[4][4] = {};
        #pragma unroll 8
        for (int c = 0; c < 64; c++) {
            float wv[4], xv[4];
            *(float4*)wv = *(float4*)&Wt[c * 64 + ty * 4];
            *(float4*)xv = *(float4*)&xs[c * 64 + tx * 4];
            #pragma unroll
            for (int i = 0; i < 4; i++)
                #pragma unroll
                for (int j = 0; j < 4; j++)
                    acc[i][j] += wv[i] * xv[j];
        }

        if (which < 2) {
            #pragma unroll
            for (int j = 0; j < 4; j++) {
                int nl = tx * 4 + j;
                #pragma unroll
                for (int i = 0; i < 4; i++) {
                    int o = ty * 4 + i;
                    float v = acc[i][j] + bs[o];
                    __nv_bfloat16 h = __float2bfloat16(v);
                    tsh[nl * PIT + o] = h;
                    tsl[nl * PIT + o] = __float2bfloat16(v - __bfloat162float(h));
                }
            }
            __syncthreads();
            for (int idx = t; idx < 64 * 8; idx += 256) {
                int row = idx >> 3, c8 = idx & 7;
                *(uint4*)&th[n0 + nc + row][c8 * 8] = *(uint4*)&tsh[row * PIT + c8 * 8];
                *(uint4*)&tl[n0 + nc + row][c8 * 8] = *(uint4*)&tsl[row * PIT + c8 * 8];
            }
        } else {
            #pragma unroll
            for (int i = 0; i < 4; i++) {
                int o = ty * 4 + i;
                float bb = bs[o];
                float v0 = acc[i][0] + bb, v1 = acc[i][1] + bb;
                float v2 = acc[i][2] + bb, v3 = acc[i][3] + bb;
                __nv_bfloat16 h0 = __float2bfloat16(v0), h1 = __float2bfloat16(v1);
                __nv_bfloat16 h2 = __float2bfloat16(v2), h3 = __float2bfloat16(v3);
                uint2 hp, lp;
                hp.x = (uint32_t)__bfloat16_as_ushort(h0) | ((uint32_t)__bfloat16_as_ushort(h1) << 16);
                hp.y = (uint32_t)__bfloat16_as_ushort(h2) | ((uint32_t)__bfloat16_as_ushort(h3) << 16);
                lp.x = pack2(v0 - __bfloat162float(h0), v1 - __bfloat162float(h1));
                lp.y = pack2(v2 - __bfloat162float(h2), v3 - __bfloat162float(h3));
                *(uint2*)&g_vh[br][b][o][n0 + nc + tx * 4] = hp;
                *(uint2*)&g_vl[br][b][o][n0 + nc + tx * 4] = lp;
            }
        }
    }
}

// ---------------------------------------------------------------------------
// Kernel 2: row stats  c_i = log2( sum_j exp(s_ij) )
// grid (32, 2, 4), block 256.  Warp grid 4x2: 32 rows x 64 cols per warp.
// smem: 2 regions of REG bytes (double-buffered K); Q staged in region 1.
// ---------------------------------------------------------------------------
__global__ void __launch_bounds__(256, 2) stats_kernel() {
    extern __shared__ char dyn[];
    __shared__ float zbuf[128];

    int t = threadIdx.x, w = t >> 5, lane = t & 31;
    int rg = w >> 1, cg = w & 1;
    int i0 = blockIdx.x * 128, br = blockIdx.y, b = blockIdx.z;

    uint32_t base = smem_u32(dyn);
    if (t < 128) zbuf[t] = 0.f;

    // prologue: Q -> region1, K[0] -> region0 via cp.async
    for (int idx = t; idx < 128 * 8; idx += 256) {
        int row = idx >> 3, c8 = idx & 7;
        uint32_t off = row * PITB + c8 * 16;
        cp16(base + REG + off,        &g_qth[br][b][i0 + row][c8 * 8]);
        cp16(base + REG + 18432 + off,&g_qtl[br][b][i0 + row][c8 * 8]);
        cp16(base + off,              &g_kth[br][b][row][c8 * 8]);
        cp16(base + 18432 + off,      &g_ktl[br][b][row][c8 * 8]);
    }
    CP_COMMIT();
    CP_WAIT0();
    __syncthreads();

    // hoist Q fragments: rows 32*rg + 16*m
    uint32_t aQh[2][4][4], aQl[2][4][4];
    #pragma unroll
    for (int m = 0; m < 2; m++) {
        uint32_t ah = base + REG +         (32 * rg + 16 * m + (lane & 15)) * PITB + (lane >> 4) * 16;
        uint32_t al = base + REG + 18432 + (32 * rg + 16 * m + (lane & 15)) * PITB + (lane >> 4) * 16;
        #pragma unroll
        for (int k = 0; k < 4; k++) { ldsm4(aQh[m][k], ah + k * 32); ldsm4(aQl[m][k], al + k * 32); }
    }
    __syncthreads();   // region1 now free for K double-buffering

    uint32_t boff = (lane & 7) * PITB + ((lane >> 3) & 1) * 16;
    float zr[4] = {0.f, 0.f, 0.f, 0.f};

    for (int jt = 0; jt < 32; jt++) {
        if (jt + 1 < 32) {
            uint32_t nb = base + ((jt + 1) & 1) * REG;
            for (int idx = t; idx < 128 * 8; idx += 256) {
                int row = idx >> 3, c8 = idx & 7;
                uint32_t off = row * PITB + c8 * 16;
                cp16(nb + off,         &g_kth[br][b][(jt + 1) * 128 + row][c8 * 8]);
                cp16(nb + 18432 + off, &g_ktl[br][b][(jt + 1) * 128 + row][c8 * 8]);
            }
            CP_COMMIT();
            CP_WAIT1();
        } else {
            CP_WAIT0();
        }
        __syncthreads();

        uint32_t kh0 = base + (jt & 1) * REG;
        uint32_t kl0 = kh0 + 18432;

        #pragma unroll
        for (int np = 0; np < 4; np++) {
            float s4[2][2][4] = {};
            #pragma unroll
            for (int k = 0; k < 4; k++) {
                uint32_t bh[2][2], bl[2][2];
                #pragma unroll
                for (int p = 0; p < 2; p++) {
                    uint32_t cb = (64 * cg + 8 * (2 * np + p)) * PITB + boff + k * 32;
                    ldsm2(bh[p], kh0 + cb);
                    ldsm2(bl[p], kl0 + cb);
                }
                #pragma unroll
                for (int p = 0; p < 2; p++)
                    #pragma unroll
                    for (int m = 0; m < 2; m++) mma_bf16(s4[p][m], aQh[m][k], bh[p]);
                #pragma unroll
                for (int p = 0; p < 2; p++)
                    #pragma unroll
                    for (int m = 0; m < 2; m++) mma_bf16(s4[p][m], aQh[m][k], bl[p]);
                #pragma unroll
                for (int p = 0; p < 2; p++)
                    #pragma unroll
                    for (int m = 0; m < 2; m++) mma_bf16(s4[p][m], aQl[m][k], bh[p]);
            }
            #pragma unroll
            for (int p = 0; p < 2; p++)
                #pragma unroll
                for (int m = 0; m < 2; m++) {
                    zr[m * 2 + 0] += ex2f(s4[p][m][0] * L2E) + ex2f(s4[p][m][1] * L2E);
                    zr[m * 2 + 1] += ex2f(s4[p][m][2] * L2E) + ex2f(s4[p][m][3] * L2E);
                }
        }
        __syncthreads();
    }

    // reduce over the 4 lanes sharing a row (lane&3), then merge col-halves
    #pragma unroll
    for (int q = 0; q < 4; q++) {
        zr[q] += __shfl_xor_sync(0xffffffffu, zr[q], 1);
        zr[q] += __shfl_xor_sync(0xffffffffu, zr[q], 2);
    }
    if ((lane & 3) == 0) {
        int rbase = 32 * rg + (lane >> 2);
        atomicAdd(&zbuf[rbase],      zr[0]);
        atomicAdd(&zbuf[rbase + 8],  zr[1]);
        atomicAdd(&zbuf[rbase + 16], zr[2]);
        atomicAdd(&zbuf[rbase + 24], zr[3]);
    }
    __syncthreads();
    if (t < 128) g_c[br][b][i0 + t] = __log2f(zbuf[t]);
}

// ---------------------------------------------------------------------------
// Kernel 3: O[c][j] = sum_i v[c][i] * 2^(s[i][j]*L2E - c_i)
// grid (32, 2, 4), block 256.  3 smem regions of REG bytes:
//   R0: K (then QV buffer A), R1: QV buffer B, R2: Ph/Pl
// QV region layout: Qh@0, Ql@9216, Vh@18432, Vl@27648
// ---------------------------------------------------------------------------
__global__ void __launch_bounds__(256, 2) pv_kernel() {
    extern __shared__ char dyn[];
    __shared__ float cs[2][64];

    int t = threadIdx.x, w = t >> 5, lane = t & 31;
    int j0 = blockIdx.x * 128, br = blockIdx.y, b = blockIdx.z;

    uint32_t base = smem_u32(dyn);
    uint32_t R2 = base + 2 * REG;       // Ph@R2, Pl@R2+18432

    // prologue: K -> R0, QV[0] -> R1
    for (int idx = t; idx < 128 * 8; idx += 256) {
        int row = idx >> 3, c8 = idx & 7;
        uint32_t off = row * PITB + c8 * 16;
        cp16(base + off,         &g_kth[br][b][j0 + row][c8 * 8]);
        cp16(base + 18432 + off, &g_ktl[br][b][j0 + row][c8 * 8]);
    }
    for (int idx = t; idx < 64 * 8; idx += 256) {
        int row = idx >> 3, c8 = idx & 7;
        uint32_t off = row * PITB + c8 * 16;
        cp16(base + REG + off,         &g_qth[br][b][row][c8 * 8]);
        cp16(base + REG + 9216 + off,  &g_qtl[br][b][row][c8 * 8]);
        cp16(base + REG + 18432 + off, &g_vh[br][b][row][c8 * 8]);
        cp16(base + REG + 27648 + off, &g_vl[br][b][row][c8 * 8]);
    }
    CP_COMMIT();
    if (t < 64) cs[0][t] = g_c[br][b][t];
    CP_WAIT0();
    __syncthreads();

    // hoist K fragments (rows 16w)
    uint32_t aKh[4][4], aKl[4][4];
    {
        uint32_t ah = base +         (16 * w + (lane & 15)) * PITB + (lane >> 4) * 16;
        uint32_t al = base + 18432 + (16 * w + (lane & 15)) * PITB + (lane >> 4) * 16;
        #pragma unroll
        for (int k = 0; k < 4; k++) { ldsm4(aKh[k], ah + k * 32); ldsm4(aKl[k], al + k * 32); }
    }
    __syncthreads();   // R0 now free

    uint32_t boff = (lane & 7) * PITB + ((lane >> 3) & 1) * 16;
    float oacc[4][2][4] = {};

    for (int it = 0; it < 64; it++) {
        uint32_t cur = base + ((it & 1) ? 0 : REG);       // QV[0] in R1, QV[1] in R0, ...
        uint32_t nxt = base + ((it & 1) ? REG : 0);

        if (it + 1 < 64) {
            int i1 = (it + 1) * 64;
            for (int idx = t; idx < 64 * 8; idx += 256) {
                int row = idx >> 3, c8 = idx & 7;
                uint32_t off = row * PITB + c8 * 16;
                cp16(nxt + off,         &g_qth[br][b][i1 + row][c8 * 8]);
                cp16(nxt + 9216 + off,  &g_qtl[br][b][i1 + row][c8 * 8]);
                cp16(nxt + 18432 + off, &g_vh[br][b][row][i1 + c8 * 8]);
                cp16(nxt + 27648 + off, &g_vl[br][b][row][i1 + c8 * 8]);
            }
            CP_COMMIT();
            if (t < 64) cs[(it + 1) & 1][t] = g_c[br][b][i1 + t];
            CP_WAIT1();
        } else {
            CP_WAIT0();
        }
        __syncthreads();

        uint32_t qh0 = cur, ql0 = cur + 9216;
        uint32_t vh0 = cur + 18432, vl0 = cur + 27648;
        const float* csc = cs[it & 1];

        // ---- S'[j][i]: rows 16w, cols 64 (2 quads of 4 n-tiles) ----
        #pragma unroll
        for (int nq = 0; nq < 2; nq++) {
            float s4[4][4] = {};
            #pragma unroll
            for (int k = 0; k < 4; k++) {
                uint32_t bh[4][2], bl[4][2];
                #pragma unroll
                for (int q = 0; q < 4; q++) {
                    uint32_t cb = (8 * (4 * nq + q)) * PITB + boff + k * 32;
                    ldsm2(bh[q], qh0 + cb);
                    ldsm2(bl[q], ql0 + cb);
                }
                #pragma unroll
                for (int q = 0; q < 4; q++) mma_bf16(s4[q], aKh[k], bh[q]);
                #pragma unroll
                for (int q = 0; q < 4; q++) mma_bf16(s4[q], aKh[k], bl[q]);
                #pragma unroll
                for (int q = 0; q < 4; q++) mma_bf16(s4[q], aKl[k], bh[q]);
            }
            #pragma unroll
            for (int q = 0; q < 4; q++) {
                int nt = 4 * nq + q;
                int col = nt * 8 + 2 * (lane & 3);
                float2 cc = *(float2*)&csc[col];
                int jr = 16 * w + (lane >> 2);
                float p0 = ex2f(fmaf(s4[q][0], L2E, -cc.x));
                float p1 = ex2f(fmaf(s4[q][1], L2E, -cc.y));
                float p2 = ex2f(fmaf(s4[q][2], L2E, -cc.x));
                float p3 = ex2f(fmaf(s4[q][3], L2E, -cc.y));
                __nv_bfloat16 h0 = __float2bfloat16(p0), h1 = __float2bfloat16(p1);
                __nv_bfloat16 h2 = __float2bfloat16(p2), h3 = __float2bfloat16(p3);
                *(uint32_t*)(dyn + 2 * REG + jr * PITB + col * 2) =
                    (uint32_t)__bfloat16_as_ushort(h0) | ((uint32_t)__bfloat16_as_ushort(h1) << 16);
                *(uint32_t*)(dyn + 2 * REG + (jr + 8) * PITB + col * 2) =
                    (uint32_t)__bfloat16_as_ushort(h2) | ((uint32_t)__bfloat16_as_ushort(h3) << 16);
                *(uint32_t*)(dyn + 2 * REG + 18432 + jr * PITB + col * 2) =
                    pack2(p0 - __bfloat162float(h0), p1 - __bfloat162float(h1));
                *(uint32_t*)(dyn + 2 * REG + 18432 + (jr + 8) * PITB + col * 2) =
                    pack2(p2 - __bfloat162float(h2), p3 - __bfloat162float(h3));
            }
        }
        __syncthreads();

        // ---- O[c][j] += V[c][i] * P[j][i] ----
        uint32_t ph0 = R2, pl0 = R2 + 18432;
        #pragma unroll
        for (int k = 0; k < 4; k++) {
            uint32_t bP[2][2], bPl[2][2];
            #pragma unroll
            for (int n2 = 0; n2 < 2; n2++) {
                uint32_t cb = (16 * w + 8 * n2) * PITB + boff + k * 32;
                ldsm2(bP[n2],  ph0 + cb);
                ldsm2(bPl[n2], pl0 + cb);
            }
            uint32_t avh[4][4], avl[4][4];
            #pragma unroll
            for (int mt = 0; mt < 4; mt++) {
                uint32_t ah = vh0 + (16 * mt + (lane & 15)) * PITB + (lane >> 4) * 16 + k * 32;
                uint32_t al = vl0 + (16 * mt + (lane & 15)) * PITB + (lane >> 4) * 16 + k * 32;
                ldsm4(avh[mt], ah);
                ldsm4(avl[mt], al);
            }
            #pragma unroll
            for (int mt = 0; mt < 4; mt++)
                #pragma unroll
                for (int n2 = 0; n2 < 2; n2++) mma_bf16(oacc[mt][n2], avh[mt], bP[n2]);
            #pragma unroll
            for (int mt = 0; mt < 4; mt++)
                #pragma unroll
                for (int n2 = 0; n2 < 2; n2++) mma_bf16(oacc[mt][n2], avh[mt], bPl[n2]);
            #pragma unroll
            for (int mt = 0; mt < 4; mt++)
                #pragma unroll
                for (int n2 = 0; n2 < 2; n2++) mma_bf16(oacc[mt][n2], avl[mt], bP[n2]);
        }
        __syncthreads();
    }

    #pragma unroll
    for (int mt = 0; mt < 4; mt++)
        #pragma unroll
        for (int n2 = 0; n2 < 2; n2++) {
            int c0 = 16 * mt + (lane >> 2);
            int jc = j0 + 16 * w + 8 * n2 + 2 * (lane & 3);
            *(float2*)&g_o[br][b][c0][jc]     = make_float2(oacc[mt][n2][0], oacc[mt][n2][1]);
            *(float2*)&g_o[br][b][c0 + 8][jc] = make_float2(oacc[mt][n2][2], oacc[mt][n2][3]);
        }
}

// ---------------------------------------------------------------------------
// Kernel 4: final fuse conv  grid (32, 4)
// ---------------------------------------------------------------------------
__global__ void __launch_bounds__(256, 2) final_kernel(const float* __restrict__ Wf,
                             const float* __restrict__ bf,
                             const float* __restrict__ g1p,
                             const float* __restrict__ g2p,
                             float* __restrict__ y) {
    extern __shared__ float smf[];
    float (*Wt)[64] = (float(*)[64])smf;
    float (*csm)[64] = (float(*)[64])(smf + 128 * 64);
    float* bs = smf + 2 * 128 * 64;

    int t = threadIdx.x;
    int b = blockIdx.y;
    int n0 = blockIdx.x * 128;
    float gg1 = *g1p, gg2 = *g2p;

    for (int idx = t; idx < 64 * 128; idx += 256) {
        int o = idx >> 7, c = idx & 127;
        Wt[c][o] = Wf[idx];
    }
    if (t < 64) bs[t] = bf[t];
    __syncthreads();

    int tx = t & 15, ty = t >> 4;
    for (int nc = 0; nc < 128; nc += 64) {
        __syncthreads();
        for (int idx = t; idx < 128 * 16; idx += 256) {
            int c = idx >> 4, n4 = idx & 15;
            const float* src = (c < 64) ? &g_o[0][b][c][0] : &g_o[1][b][c - 64][0];
            float g = (c < 64) ? gg1 : gg2;
            float4 v4 = *(const float4*)&src[n0 + nc + n4 * 4];
            v4.x *= g; v4.y *= g; v4.z *= g; v4.w *= g;
            *(float4*)&csm[c][n4 * 4] = v4;
        }
        __syncthreads();

        float acc[4][4] = {};
        #pragma unroll 8
        for (int c = 0; c < 128; c++) {
            float wv[4], xv[4];
            *(float4*)wv = *(float4*)&Wt[c][ty * 4];
            *(float4*)xv = *(float4*)&csm[c][tx * 4];
            #pragma unroll
            for (int i = 0; i < 4; i++)
                #pragma unroll
                for (int j = 0; j < 4; j++)
                    acc[i][j] += wv[i] * xv[j];
        }
        #pragma unroll
        for (int i = 0; i < 4; i++) {
            int o = ty * 4 + i;
            float bb = bs[o];
            float4 r = make_float4(acc[i][0] + bb, acc[i][1] + bb,
                                   acc[i][2] + bb, acc[i][3] + bb);
            *(float4*)&y[(size_t)b * 64 * NTOK + o * NTOK + n0 + nc + tx * 4] = r;
        }
    }
}

// ---------------------------------------------------------------------------
extern "C" void kernel_launch(void* const* d_in, const int* in_sizes, int n_in,
                              void* d_out, int out_size) {
    const float* x  = (const float*)d_in[0];
    const float* g1 = (const float*)d_in[13];
    const float* g2 = (const float*)d_in[14];
    const float* Wf = (const float*)d_in[15];
    const float* bf = (const float*)d_in[16];
    float* y = (float*)d_out;

    ProjArgs pa;
    for (int mi = 0; mi < 6; mi++) {
        pa.W[mi] = (const float*)d_in[1 + 2 * mi];
        pa.B[mi] = (const float*)d_in[2 + 2 * mi];
    }

    const int smP = (4096 + 4096 + 64) * 4 + 2 * 64 * PIT * 2;   // 51456
    const int smS = 2 * REG;                                     // 73728
    const int smV = 3 * REG;                                     // 110592
    const int smF = (2 * 128 * 64 + 64) * 4;                     // 65792

    cudaFuncSetAttribute(proj_kernel,  cudaFuncAttributeMaxDynamicSharedMemorySize, smP);
    cudaFuncSetAttribute(stats_kernel, cudaFuncAttributeMaxDynamicSharedMemorySize, smS);
    cudaFuncSetAttribute(pv_kernel,    cudaFuncAttributeMaxDynamicSharedMemorySize, smV);
    cudaFuncSetAttribute(final_kernel, cudaFuncAttributeMaxDynamicSharedMemorySize, smF);

    proj_kernel<<<dim3(16, 4, 6), 256, smP>>>(x, pa);
    stats_kernel<<<dim3(32, 2, 4), 256, smS>>>();
    pv_kernel<<<dim3(32, 2, 4), 256, smV>>>();
    final_kernel<<<dim3(32, 4), 256, smF>>>(Wf, bf, g1, g2, y);
}

// round 8
// speedup vs baseline: 3.5557x; 1.0598x over previous
#include <cuda_runtime.h>
#include <cuda_bf16.h>
#include <cstdint>

#define NTOK 4096
#define L2E  1.4426950408889634f
#define PIT  72          // smem pitch in bf16 elements
#define PITB 144         // smem pitch in bytes
#define REG  36864       // region size: 128 rows * 144B * 2 (hi+lo)

// ---------------- scratch ----------------
__device__ __nv_bfloat16 g_qth[2][4][NTOK][64];
__device__ __nv_bfloat16 g_qtl[2][4][NTOK][64];
__device__ __nv_bfloat16 g_kth[2][4][NTOK][64];
__device__ __nv_bfloat16 g_ktl[2][4][NTOK][64];
__device__ __nv_bfloat16 g_vh [2][4][64][NTOK];
__device__ __nv_bfloat16 g_vl [2][4][64][NTOK];
__device__ float g_c[2][4][NTOK];
__device__ float g_ot[2][4][NTOK][64];   // O transposed: [token j][chan c]

// ---------------- helpers ----------------
__device__ __forceinline__ uint32_t smem_u32(const void* p) {
    uint32_t a;
    asm("{ .reg .u64 t; cvta.to.shared.u64 t, %1; cvt.u32.u64 %0, t; }" : "=r"(a) : "l"(p));
    return a;
}
__device__ __forceinline__ float ex2f(float x) {
    float r; asm("ex2.approx.ftz.f32 %0, %1;" : "=f"(r) : "f"(x)); return r;
}
__device__ __forceinline__ void ldsm4(uint32_t* r, uint32_t a) {
    asm volatile("ldmatrix.sync.aligned.m8n8.x4.shared.b16 {%0,%1,%2,%3}, [%4];"
                 : "=r"(r[0]), "=r"(r[1]), "=r"(r[2]), "=r"(r[3]) : "r"(a));
}
__device__ __forceinline__ void ldsm2(uint32_t* r, uint32_t a) {
    asm volatile("ldmatrix.sync.aligned.m8n8.x2.shared.b16 {%0,%1}, [%2];"
                 : "=r"(r[0]), "=r"(r[1]) : "r"(a));
}
__device__ __forceinline__ void mma_bf16(float* c, const uint32_t* a, const uint32_t* b) {
    asm volatile("mma.sync.aligned.m16n8k16.row.col.f32.bf16.bf16.f32 "
                 "{%0,%1,%2,%3}, {%4,%5,%6,%7}, {%8,%9}, {%0,%1,%2,%3};"
                 : "+f"(c[0]), "+f"(c[1]), "+f"(c[2]), "+f"(c[3])
                 : "r"(a[0]), "r"(a[1]), "r"(a[2]), "r"(a[3]), "r"(b[0]), "r"(b[1]));
}
__device__ __forceinline__ uint32_t pack2(float a, float b) {
    __nv_bfloat16 ha = __float2bfloat16(a), hb = __float2bfloat16(b);
    return (uint32_t)__bfloat16_as_ushort(ha) | ((uint32_t)__bfloat16_as_ushort(hb) << 16);
}
__device__ __forceinline__ void cp16(uint32_t d, const void* s) {
    asm volatile("cp.async.cg.shared.global [%0], [%1], 16;" :: "r"(d), "l"(s));
}
#define CP_COMMIT() asm volatile("cp.async.commit_group;" ::: "memory")
#define CP_WAIT0()  asm volatile("cp.async.wait_group 0;" ::: "memory")
#define CP_WAIT1()  asm volatile("cp.async.wait_group 1;" ::: "memory")

// ---------------------------------------------------------------------------
// Kernel 1: fused projections -> bf16 hi/lo in MMA-ready (k-contiguous) layouts
// ---------------------------------------------------------------------------
struct ProjArgs { const float* W[6]; const float* B[6]; };

__global__ void __launch_bounds__(256, 2) proj_kernel(const float* __restrict__ x, ProjArgs pa) {
    extern __shared__ char dsm[];
    float* Wt = (float*)dsm;
    float* xs = Wt + 4096;
    float* bs = xs + 4096;
    __nv_bfloat16* tsh = (__nv_bfloat16*)(bs + 64);
    __nv_bfloat16* tsl = tsh + 64 * PIT;

    int t = threadIdx.x;
    int b = blockIdx.y;
    int n0 = blockIdx.x * 256;
    int z = blockIdx.z, br = z / 3, which = z % 3;
    const float* W = pa.W[z];
    const float* bias = pa.B[z];

    for (int idx = t; idx < 64 * 64; idx += 256) {
        int o = idx >> 6, c = idx & 63;
        Wt[c * 64 + o] = W[idx];
    }
    if (t < 64) bs[t] = bias[t];
    __syncthreads();

    const float* xb = x + (size_t)b * 64 * NTOK;
    int tx = t & 15, ty = t >> 4;

    __nv_bfloat16 (*th)[64] = (which == 0) ? g_qth[br][b] : g_kth[br][b];
    __nv_bfloat16 (*tl)[64] = (which == 0) ? g_qtl[br][b] : g_ktl[br][b];

    for (int nc = 0; nc < 256; nc += 64) {
        __syncthreads();
        for (int idx = t; idx < 64 * 16; idx += 256) {
            int c = idx >> 4, n4 = idx & 15;
            *(float4*)&xs[c * 64 + n4 * 4] = *(const float4*)&xb[c * NTOK + n0 + nc + n4 * 4];
        }
        __syncthreads();

        float acc[4][4] = {};
        #pragma unroll 8
        for (int c = 0; c < 64; c++) {
            float wv[4], xv[4];
            *(float4*)wv = *(float4*)&Wt[c * 64 + ty * 4];
            *(float4*)xv = *(float4*)&xs[c * 64 + tx * 4];
            #pragma unroll
            for (int i = 0; i < 4; i++)
                #pragma unroll
                for (int j = 0; j < 4; j++)
                    acc[i][j] += wv[i] * xv[j];
        }

        if (which < 2) {
            #pragma unroll
            for (int j = 0; j < 4; j++) {
                int nl = tx * 4 + j;
                #pragma unroll
                for (int i = 0; i < 4; i++) {
                    int o = ty * 4 + i;
                    float v = acc[i][j] + bs[o];
                    __nv_bfloat16 h = __float2bfloat16(v);
                    tsh[nl * PIT + o] = h;
                    tsl[nl * PIT + o] = __float2bfloat16(v - __bfloat162float(h));
                }
            }
            __syncthreads();
            for (int idx = t; idx < 64 * 8; idx += 256) {
                int row = idx >> 3, c8 = idx & 7;
                *(uint4*)&th[n0 + nc + row][c8 * 8] = *(uint4*)&tsh[row * PIT + c8 * 8];
                *(uint4*)&tl[n0 + nc + row][c8 * 8] = *(uint4*)&tsl[row * PIT + c8 * 8];
            }
        } else {
            #pragma unroll
            for (int i = 0; i < 4; i++) {
                int o = ty * 4 + i;
                float bb = bs[o];
                float v0 = acc[i][0] + bb, v1 = acc[i][1] + bb;
                float v2 = acc[i][2] + bb, v3 = acc[i][3] + bb;
                __nv_bfloat16 h0 = __float2bfloat16(v0), h1 = __float2bfloat16(v1);
                __nv_bfloat16 h2 = __float2bfloat16(v2), h3 = __float2bfloat16(v3);
                uint2 hp, lp;
                hp.x = (uint32_t)__bfloat16_as_ushort(h0) | ((uint32_t)__bfloat16_as_ushort(h1) << 16);
                hp.y = (uint32_t)__bfloat16_as_ushort(h2) | ((uint32_t)__bfloat16_as_ushort(h3) << 16);
                lp.x = pack2(v0 - __bfloat162float(h0), v1 - __bfloat162float(h1));
                lp.y = pack2(v2 - __bfloat162float(h2), v3 - __bfloat162float(h3));
                *(uint2*)&g_vh[br][b][o][n0 + nc + tx * 4] = hp;
                *(uint2*)&g_vl[br][b][o][n0 + nc + tx * 4] = lp;
            }
        }
    }
}

// ---------------------------------------------------------------------------
// Kernel 2: row stats  c_i = log2( sum_j exp(s_ij) )
// ---------------------------------------------------------------------------
__global__ void __launch_bounds__(256, 2) stats_kernel() {
    extern __shared__ char dyn[];
    __shared__ float zbuf[128];

    int t = threadIdx.x, w = t >> 5, lane = t & 31;
    int rg = w >> 1, cg = w & 1;
    int i0 = blockIdx.x * 128, br = blockIdx.y, b = blockIdx.z;

    uint32_t base = smem_u32(dyn);
    if (t < 128) zbuf[t] = 0.f;

    for (int idx = t; idx < 128 * 8; idx += 256) {
        int row = idx >> 3, c8 = idx & 7;
        uint32_t off = row * PITB + c8 * 16;
        cp16(base + REG + off,        &g_qth[br][b][i0 + row][c8 * 8]);
        cp16(base + REG + 18432 + off,&g_qtl[br][b][i0 + row][c8 * 8]);
        cp16(base + off,              &g_kth[br][b][row][c8 * 8]);
        cp16(base + 18432 + off,      &g_ktl[br][b][row][c8 * 8]);
    }
    CP_COMMIT();
    CP_WAIT0();
    __syncthreads();

    uint32_t aQh[2][4][4], aQl[2][4][4];
    #pragma unroll
    for (int m = 0; m < 2; m++) {
        uint32_t ah = base + REG +         (32 * rg + 16 * m + (lane & 15)) * PITB + (lane >> 4) * 16;
        uint32_t al = base + REG + 18432 + (32 * rg + 16 * m + (lane & 15)) * PITB + (lane >> 4) * 16;
        #pragma unroll
        for (int k = 0; k < 4; k++) { ldsm4(aQh[m][k], ah + k * 32); ldsm4(aQl[m][k], al + k * 32); }
    }
    __syncthreads();

    uint32_t boff = (lane & 7) * PITB + ((lane >> 3) & 1) * 16;
    float zr[4] = {0.f, 0.f, 0.f, 0.f};

    for (int jt = 0; jt < 32; jt++) {
        if (jt + 1 < 32) {
            uint32_t nb = base + ((jt + 1) & 1) * REG;
            for (int idx = t; idx < 128 * 8; idx += 256) {
                int row = idx >> 3, c8 = idx & 7;
                uint32_t off = row * PITB + c8 * 16;
                cp16(nb + off,         &g_kth[br][b][(jt + 1) * 128 + row][c8 * 8]);
                cp16(nb + 18432 + off, &g_ktl[br][b][(jt + 1) * 128 + row][c8 * 8]);
            }
            CP_COMMIT();
            CP_WAIT1();
        } else {
            CP_WAIT0();
        }
        __syncthreads();

        uint32_t kh0 = base + (jt & 1) * REG;
        uint32_t kl0 = kh0 + 18432;

        #pragma unroll
        for (int np = 0; np < 4; np++) {
            float s4[2][2][4] = {};
            #pragma unroll
            for (int k = 0; k < 4; k++) {
                uint32_t bh[2][2], bl[2][2];
                #pragma unroll
                for (int p = 0; p < 2; p++) {
                    uint32_t cb = (64 * cg + 8 * (2 * np + p)) * PITB + boff + k * 32;
                    ldsm2(bh[p], kh0 + cb);
                    ldsm2(bl[p], kl0 + cb);
                }
                #pragma unroll
                for (int p = 0; p < 2; p++)
                    #pragma unroll
                    for (int m = 0; m < 2; m++) mma_bf16(s4[p][m], aQh[m][k], bh[p]);
                #pragma unroll
                for (int p = 0; p < 2; p++)
                    #pragma unroll
                    for (int m = 0; m < 2; m++) mma_bf16(s4[p][m], aQh[m][k], bl[p]);
                #pragma unroll
                for (int p = 0; p < 2; p++)
                    #pragma unroll
                    for (int m = 0; m < 2; m++) mma_bf16(s4[p][m], aQl[m][k], bh[p]);
            }
            #pragma unroll
            for (int p = 0; p < 2; p++)
                #pragma unroll
                for (int m = 0; m < 2; m++) {
                    zr[m * 2 + 0] += ex2f(s4[p][m][0] * L2E) + ex2f(s4[p][m][1] * L2E);
                    zr[m * 2 + 1] += ex2f(s4[p][m][2] * L2E) + ex2f(s4[p][m][3] * L2E);
                }
        }
        __syncthreads();
    }

    #pragma unroll
    for (int q = 0; q < 4; q++) {
        zr[q] += __shfl_xor_sync(0xffffffffu, zr[q], 1);
        zr[q] += __shfl_xor_sync(0xffffffffu, zr[q], 2);
    }
    if ((lane & 3) == 0) {
        int rbase = 32 * rg + (lane >> 2);
        atomicAdd(&zbuf[rbase],      zr[0]);
        atomicAdd(&zbuf[rbase + 8],  zr[1]);
        atomicAdd(&zbuf[rbase + 16], zr[2]);
        atomicAdd(&zbuf[rbase + 24], zr[3]);
    }
    __syncthreads();
    if (t < 128) g_c[br][b][i0 + t] = __log2f(zbuf[t]);
}

// ---------------------------------------------------------------------------
// Kernel 3: O[j][c] = sum_i 2^(s[j][i]*L2E - c_i) * v[c][i]
// P stays in registers (acc m16n8 -> A m16k16 repack). One barrier per iter.
// ---------------------------------------------------------------------------
__global__ void __launch_bounds__(256, 2) pv_kernel() {
    extern __shared__ char dyn[];
    __shared__ float cs[2][64];

    int t = threadIdx.x, w = t >> 5, lane = t & 31;
    int j0 = blockIdx.x * 128, br = blockIdx.y, b = blockIdx.z;

    uint32_t base = smem_u32(dyn);

    for (int idx = t; idx < 128 * 8; idx += 256) {
        int row = idx >> 3, c8 = idx & 7;
        uint32_t off = row * PITB + c8 * 16;
        cp16(base + off,         &g_kth[br][b][j0 + row][c8 * 8]);
        cp16(base + 18432 + off, &g_ktl[br][b][j0 + row][c8 * 8]);
    }
    for (int idx = t; idx < 64 * 8; idx += 256) {
        int row = idx >> 3, c8 = idx & 7;
        uint32_t off = row * PITB + c8 * 16;
        cp16(base + REG + off,         &g_qth[br][b][row][c8 * 8]);
        cp16(base + REG + 9216 + off,  &g_qtl[br][b][row][c8 * 8]);
        cp16(base + REG + 18432 + off, &g_vh[br][b][row][c8 * 8]);
        cp16(base + REG + 27648 + off, &g_vl[br][b][row][c8 * 8]);
    }
    CP_COMMIT();
    if (t < 64) cs[0][t] = g_c[br][b][t];
    CP_WAIT0();
    __syncthreads();

    uint32_t aKh[4][4], aKl[4][4];
    {
        uint32_t ah = base +         (16 * w + (lane & 15)) * PITB + (lane >> 4) * 16;
        uint32_t al = base + 18432 + (16 * w + (lane & 15)) * PITB + (lane >> 4) * 16;
        #pragma unroll
        for (int k = 0; k < 4; k++) { ldsm4(aKh[k], ah + k * 32); ldsm4(aKl[k], al + k * 32); }
    }

    uint32_t boff = (lane & 7) * PITB + ((lane >> 3) & 1) * 16;
    float oacc[8][4] = {};

    for (int it = 0; it < 64; it++) {
        uint32_t cur = base + ((it & 1) ? 0 : REG);
        uint32_t nxt = base + ((it & 1) ? REG : 0);

        CP_WAIT0();
        __syncthreads();

        if (it + 1 < 64) {
            int i1 = (it + 1) * 64;
            for (int idx = t; idx < 64 * 8; idx += 256) {
                int row = idx >> 3, c8 = idx & 7;
                uint32_t off = row * PITB + c8 * 16;
                cp16(nxt + off,         &g_qth[br][b][i1 + row][c8 * 8]);
                cp16(nxt + 9216 + off,  &g_qtl[br][b][i1 + row][c8 * 8]);
                cp16(nxt + 18432 + off, &g_vh[br][b][row][i1 + c8 * 8]);
                cp16(nxt + 27648 + off, &g_vl[br][b][row][i1 + c8 * 8]);
            }
            CP_COMMIT();
            if (t < 64) cs[(it + 1) & 1][t] = g_c[br][b][i1 + t];
        }

        uint32_t qh0 = cur, ql0 = cur + 9216;
        uint32_t vh0 = cur + 18432, vl0 = cur + 27648;
        const float* csc = cs[it & 1];

        #pragma unroll
        for (int h = 0; h < 2; h++) {
            float s4[4][4] = {};
            #pragma unroll
            for (int k = 0; k < 4; k++) {
                uint32_t bh[4][2], bl[4][2];
                #pragma unroll
                for (int q = 0; q < 4; q++) {
                    uint32_t cb = (8 * (4 * h + q)) * PITB + boff + k * 32;
                    ldsm2(bh[q], qh0 + cb);
                    ldsm2(bl[q], ql0 + cb);
                }
                #pragma unroll
                for (int q = 0; q < 4; q++) mma_bf16(s4[q], aKh[k], bh[q]);
                #pragma unroll
                for (int q = 0; q < 4; q++) mma_bf16(s4[q], aKh[k], bl[q]);
                #pragma unroll
                for (int q = 0; q < 4; q++) mma_bf16(s4[q], aKl[k], bh[q]);
            }

            #pragma unroll
            for (int kc = 0; kc < 2; kc++) {
                uint32_t aP[4], aPl[4];
                #pragma unroll
                for (int qq = 0; qq < 2; qq++) {
                    int q = 2 * kc + qq;
                    int col = 8 * (4 * h + q) + 2 * (lane & 3);
                    float2 cc = *(float2*)&csc[col];
                    float p0 = ex2f(fmaf(s4[q][0], L2E, -cc.x));
                    float p1 = ex2f(fmaf(s4[q][1], L2E, -cc.y));
                    float p2 = ex2f(fmaf(s4[q][2], L2E, -cc.x));
                    float p3 = ex2f(fmaf(s4[q][3], L2E, -cc.y));
                    __nv_bfloat16 h0 = __float2bfloat16(p0), h1 = __float2bfloat16(p1);
                    __nv_bfloat16 h2 = __float2bfloat16(p2), h3 = __float2bfloat16(p3);
                    aP[qq * 2 + 0] = (uint32_t)__bfloat16_as_ushort(h0) |
                                     ((uint32_t)__bfloat16_as_ushort(h1) << 16);
                    aP[qq * 2 + 1] = (uint32_t)__bfloat16_as_ushort(h2) |
                                     ((uint32_t)__bfloat16_as_ushort(h3) << 16);
                    aPl[qq * 2 + 0] = pack2(p0 - __bfloat162float(h0), p1 - __bfloat162float(h1));
                    aPl[qq * 2 + 1] = pack2(p2 - __bfloat162float(h2), p3 - __bfloat162float(h3));
                }

                uint32_t kb = (uint32_t)(64 * h + 32 * kc);
                #pragma unroll
                for (int cg2 = 0; cg2 < 2; cg2++) {
                    uint32_t bVh[4][2], bVl[4][2];
                    #pragma unroll
                    for (int c4 = 0; c4 < 4; c4++) {
                        uint32_t cb = (8 * (4 * cg2 + c4)) * PITB + boff + kb;
                        ldsm2(bVh[c4], vh0 + cb);
                        ldsm2(bVl[c4], vl0 + cb);
                    }
                    #pragma unroll
                    for (int c4 = 0; c4 < 4; c4++) mma_bf16(oacc[4 * cg2 + c4], aP, bVh[c4]);
                    #pragma unroll
                    for (int c4 = 0; c4 < 4; c4++) mma_bf16(oacc[4 * cg2 + c4], aP, bVl[c4]);
                    #pragma unroll
                    for (int c4 = 0; c4 < 4; c4++) mma_bf16(oacc[4 * cg2 + c4], aPl, bVh[c4]);
                }
            }
        }
    }

    int jr = j0 + 16 * w + (lane >> 2);
    #pragma unroll
    for (int ct = 0; ct < 8; ct++) {
        int c0 = 8 * ct + 2 * (lane & 3);
        *(float2*)&g_ot[br][b][jr][c0]     = make_float2(oacc[ct][0], oacc[ct][1]);
        *(float2*)&g_ot[br][b][jr + 8][c0] = make_float2(oacc[ct][2], oacc[ct][3]);
    }
}

// ---------------------------------------------------------------------------
// Kernel 4: final fuse conv, reads g_ot with smem transpose staging
// ---------------------------------------------------------------------------
__global__ void __launch_bounds__(256, 2) final_kernel(const float* __restrict__ Wf,
                             const float* __restrict__ bf,
                             const float* __restrict__ g1p,
                             const float* __restrict__ g2p,
                             float* __restrict__ y) {
    extern __shared__ float smf[];
    float (*Wt)[64] = (float(*)[64])smf;                    // [128][64]
    float (*csm)[68] = (float(*)[68])(smf + 128 * 64);      // [128][68] padded
    float* bs = smf + 128 * 64 + 128 * 68;

    int t = threadIdx.x;
    int b = blockIdx.y;
    int n0 = blockIdx.x * 128;
    float gg1 = *g1p, gg2 = *g2p;

    for (int idx = t; idx < 64 * 128; idx += 256) {
        int o = idx >> 7, c = idx & 127;
        Wt[c][o] = Wf[idx];
    }
    if (t < 64) bs[t] = bf[t];
    __syncthreads();

    int tx = t & 15, ty = t >> 4;
    for (int nc = 0; nc < 128; nc += 64) {
        __syncthreads();
        // transpose-stage: 2 branches x 64 tokens x 64 chans = 2048 float4 reads
        for (int idx = t; idx < 2048; idx += 256) {
            int br2 = idx >> 10, rem = idx & 1023, n = rem >> 4, c4 = rem & 15;
            float4 v4 = *(const float4*)&g_ot[br2][b][n0 + nc + n][c4 * 4];
            float g = br2 ? gg2 : gg1;
            csm[br2 * 64 + c4 * 4 + 0][n] = v4.x * g;
            csm[br2 * 64 + c4 * 4 + 1][n] = v4.y * g;
            csm[br2 * 64 + c4 * 4 + 2][n] = v4.z * g;
            csm[br2 * 64 + c4 * 4 + 3][n] = v4.w * g;
        }
        __syncthreads();

        float acc[4][4] = {};
        #pragma unroll 8
        for (int c = 0; c < 128; c++) {
            float wv[4], xv[4];
            *(float4*)wv = *(float4*)&Wt[c][ty * 4];
            *(float4*)xv = *(float4*)&csm[c][tx * 4];
            #pragma unroll
            for (int i = 0; i < 4; i++)
                #pragma unroll
                for (int j = 0; j < 4; j++)
                    acc[i][j] += wv[i] * xv[j];
        }
        #pragma unroll
        for (int i = 0; i < 4; i++) {
            int o = ty * 4 + i;
            float bb = bs[o];
            float4 r = make_float4(acc[i][0] + bb, acc[i][1] + bb,
                                   acc[i][2] + bb, acc[i][3] + bb);
            *(float4*)&y[(size_t)b * 64 * NTOK + o * NTOK + n0 + nc + tx * 4] = r;
        }
    }
}

// ---------------------------------------------------------------------------
extern "C" void kernel_launch(void* const* d_in, const int* in_sizes, int n_in,
                              void* d_out, int out_size) {
    const float* x  = (const float*)d_in[0];
    const float* g1 = (const float*)d_in[13];
    const float* g2 = (const float*)d_in[14];
    const float* Wf = (const float*)d_in[15];
    const float* bf = (const float*)d_in[16];
    float* y = (float*)d_out;

    ProjArgs pa;
    for (int mi = 0; mi < 6; mi++) {
        pa.W[mi] = (const float*)d_in[1 + 2 * mi];
        pa.B[mi] = (const float*)d_in[2 + 2 * mi];
    }

    const int smP = (4096 + 4096 + 64) * 4 + 2 * 64 * PIT * 2;   // 51456
    const int smS = 2 * REG;                                     // 73728
    const int smV = 2 * REG;                                     // 73728
    const int smF = (128 * 64 + 128 * 68 + 64) * 4;              // 67840

    cudaFuncSetAttribute(proj_kernel,  cudaFuncAttributeMaxDynamicSharedMemorySize, smP);
    cudaFuncSetAttribute(stats_kernel, cudaFuncAttributeMaxDynamicSharedMemorySize, smS);
    cudaFuncSetAttribute(pv_kernel,    cudaFuncAttributeMaxDynamicSharedMemorySize, smV);
    cudaFuncSetAttribute(final_kernel, cudaFuncAttributeMaxDynamicSharedMemorySize, smF);

    proj_kernel<<<dim3(16, 4, 6), 256, smP>>>(x, pa);
    stats_kernel<<<dim3(32, 2, 4), 256, smS>>>();
    pv_kernel<<<dim3(32, 2, 4), 256, smV>>>();
    final_kernel<<<dim3(32, 4), 256, smF>>>(Wf, bf, g1, g2, y);
}

// round 9
// speedup vs baseline: 3.6548x; 1.0279x over previous
#include <cuda_runtime.h>
#include <cuda_bf16.h>
#include <cstdint>

#define NTOK 4096
#define L2E  1.4426950408889634f
#define PIT  72          // smem pitch in bf16 elements
#define PITB 144         // smem pitch in bytes
#define REG  36864       // region size: 128 rows * 144B * 2 (hi+lo)

// ---------------- scratch ----------------
__device__ __nv_bfloat16 g_qth[2][4][NTOK][64];
__device__ __nv_bfloat16 g_qtl[2][4][NTOK][64];
__device__ __nv_bfloat16 g_kth[2][4][NTOK][64];
__device__ __nv_bfloat16 g_ktl[2][4][NTOK][64];
__device__ __nv_bfloat16 g_vh [2][4][64][NTOK];
__device__ __nv_bfloat16 g_vl [2][4][64][NTOK];
__device__ float g_c[2][4][NTOK];
__device__ float g_ot[2][4][NTOK][64];   // O transposed: [token j][chan c]

// ---------------- helpers ----------------
__device__ __forceinline__ uint32_t smem_u32(const void* p) {
    uint32_t a;
    asm("{ .reg .u64 t; cvta.to.shared.u64 t, %1; cvt.u32.u64 %0, t; }" : "=r"(a) : "l"(p));
    return a;
}
__device__ __forceinline__ float ex2f(float x) {
    float r; asm("ex2.approx.ftz.f32 %0, %1;" : "=f"(r) : "f"(x)); return r;
}
__device__ __forceinline__ void ldsm4(uint32_t* r, uint32_t a) {
    asm volatile("ldmatrix.sync.aligned.m8n8.x4.shared.b16 {%0,%1,%2,%3}, [%4];"
                 : "=r"(r[0]), "=r"(r[1]), "=r"(r[2]), "=r"(r[3]) : "r"(a));
}
__device__ __forceinline__ void ldsm2(uint32_t* r, uint32_t a) {
    asm volatile("ldmatrix.sync.aligned.m8n8.x2.shared.b16 {%0,%1}, [%2];"
                 : "=r"(r[0]), "=r"(r[1]) : "r"(a));
}
__device__ __forceinline__ void mma_bf16(float* c, const uint32_t* a, const uint32_t* b) {
    asm volatile("mma.sync.aligned.m16n8k16.row.col.f32.bf16.bf16.f32 "
                 "{%0,%1,%2,%3}, {%4,%5,%6,%7}, {%8,%9}, {%0,%1,%2,%3};"
                 : "+f"(c[0]), "+f"(c[1]), "+f"(c[2]), "+f"(c[3])
                 : "r"(a[0]), "r"(a[1]), "r"(a[2]), "r"(a[3]), "r"(b[0]), "r"(b[1]));
}
// packed bf16x2 convert: lo = a, hi = b (rn rounding, same as __float2bfloat16)
__device__ __forceinline__ uint32_t cvtb2(float a, float b) {
    uint32_t r;
    asm("cvt.rn.bf16x2.f32 %0, %1, %2;" : "=r"(r) : "f"(b), "f"(a));
    return r;
}
__device__ __forceinline__ void cp16(uint32_t d, const void* s) {
    asm volatile("cp.async.cg.shared.global [%0], [%1], 16;" :: "r"(d), "l"(s));
}
#define CP_COMMIT() asm volatile("cp.async.commit_group;" ::: "memory")
#define CP_WAIT0()  asm volatile("cp.async.wait_group 0;" ::: "memory")

// ---------------------------------------------------------------------------
// Kernel 1: fused projections -> bf16 hi/lo in MMA-ready (k-contiguous) layouts
// ---------------------------------------------------------------------------
struct ProjArgs { const float* W[6]; const float* B[6]; };

__global__ void __launch_bounds__(256, 2) proj_kernel(const float* __restrict__ x, ProjArgs pa) {
    extern __shared__ char dsm[];
    float* Wt = (float*)dsm;
    float* xs = Wt + 4096;
    float* bs = xs + 4096;
    __nv_bfloat16* tsh = (__nv_bfloat16*)(bs + 64);
    __nv_bfloat16* tsl = tsh + 64 * PIT;

    int t = threadIdx.x;
    int b = blockIdx.y;
    int n0 = blockIdx.x * 256;
    int z = blockIdx.z, br = z / 3, which = z % 3;
    const float* W = pa.W[z];
    const float* bias = pa.B[z];

    for (int idx = t; idx < 64 * 64; idx += 256) {
        int o = idx >> 6, c = idx & 63;
        Wt[c * 64 + o] = W[idx];
    }
    if (t < 64) bs[t] = bias[t];
    __syncthreads();

    const float* xb = x + (size_t)b * 64 * NTOK;
    int tx = t & 15, ty = t >> 4;

    __nv_bfloat16 (*th)[64] = (which == 0) ? g_qth[br][b] : g_kth[br][b];
    __nv_bfloat16 (*tl)[64] = (which == 0) ? g_qtl[br][b] : g_ktl[br][b];

    for (int nc = 0; nc < 256; nc += 64) {
        __syncthreads();
        for (int idx = t; idx < 64 * 16; idx += 256) {
            int c = idx >> 4, n4 = idx & 15;
            *(float4*)&xs[c * 64 + n4 * 4] = *(const float4*)&xb[c * NTOK + n0 + nc + n4 * 4];
        }
        __syncthreads();

        float acc[4][4] = {};
        #pragma unroll 8
        for (int c = 0; c < 64; c++) {
            float wv[4], xv[4];
            *(float4*)wv = *(float4*)&Wt[c * 64 + ty * 4];
            *(float4*)xv = *(float4*)&xs[c * 64 + tx * 4];
            #pragma unroll
            for (int i = 0; i < 4; i++)
                #pragma unroll
                for (int j = 0; j < 4; j++)
                    acc[i][j] += wv[i] * xv[j];
        }

        if (which < 2) {
            #pragma unroll
            for (int j = 0; j < 4; j++) {
                int nl = tx * 4 + j;
                #pragma unroll
                for (int i = 0; i < 4; i++) {
                    int o = ty * 4 + i;
                    float v = acc[i][j] + bs[o];
                    __nv_bfloat16 h = __float2bfloat16(v);
                    tsh[nl * PIT + o] = h;
                    tsl[nl * PIT + o] = __float2bfloat16(v - __bfloat162float(h));
                }
            }
            __syncthreads();
            for (int idx = t; idx < 64 * 8; idx += 256) {
                int row = idx >> 3, c8 = idx & 7;
                *(uint4*)&th[n0 + nc + row][c8 * 8] = *(uint4*)&tsh[row * PIT + c8 * 8];
                *(uint4*)&tl[n0 + nc + row][c8 * 8] = *(uint4*)&tsl[row * PIT + c8 * 8];
            }
        } else {
            #pragma unroll
            for (int i = 0; i < 4; i++) {
                int o = ty * 4 + i;
                float bb = bs[o];
                float v0 = acc[i][0] + bb, v1 = acc[i][1] + bb;
                float v2 = acc[i][2] + bb, v3 = acc[i][3] + bb;
                uint2 hp, lp;
                hp.x = cvtb2(v0, v1);
                hp.y = cvtb2(v2, v3);
                float h0 = __uint_as_float(hp.x << 16);
                float h1 = __uint_as_float(hp.x & 0xFFFF0000u);
                float h2 = __uint_as_float(hp.y << 16);
                float h3 = __uint_as_float(hp.y & 0xFFFF0000u);
                lp.x = cvtb2(v0 - h0, v1 - h1);
                lp.y = cvtb2(v2 - h2, v3 - h3);
                *(uint2*)&g_vh[br][b][o][n0 + nc + tx * 4] = hp;
                *(uint2*)&g_vl[br][b][o][n0 + nc + tx * 4] = lp;
            }
        }
    }
}

// ---------------------------------------------------------------------------
// Kernel 2: row stats  c_i = log2( sum_j exp(s_ij) )
// Single barrier per iteration; prefetch issued after the barrier.
// ---------------------------------------------------------------------------
__global__ void __launch_bounds__(256, 2) stats_kernel() {
    extern __shared__ char dyn[];
    __shared__ float zbuf[128];

    int t = threadIdx.x, w = t >> 5, lane = t & 31;
    int rg = w >> 1, cg = w & 1;
    int i0 = blockIdx.x * 128, br = blockIdx.y, b = blockIdx.z;

    uint32_t base = smem_u32(dyn);
    if (t < 128) zbuf[t] = 0.f;

    // prologue: Q -> region1, K[0] -> region0
    for (int idx = t; idx < 128 * 8; idx += 256) {
        int row = idx >> 3, c8 = idx & 7;
        uint32_t off = row * PITB + c8 * 16;
        cp16(base + REG + off,        &g_qth[br][b][i0 + row][c8 * 8]);
        cp16(base + REG + 18432 + off,&g_qtl[br][b][i0 + row][c8 * 8]);
        cp16(base + off,              &g_kth[br][b][row][c8 * 8]);
        cp16(base + 18432 + off,      &g_ktl[br][b][row][c8 * 8]);
    }
    CP_COMMIT();
    CP_WAIT0();
    __syncthreads();

    uint32_t aQh[2][4][4], aQl[2][4][4];
    #pragma unroll
    for (int m = 0; m < 2; m++) {
        uint32_t ah = base + REG +         (32 * rg + 16 * m + (lane & 15)) * PITB + (lane >> 4) * 16;
        uint32_t al = base + REG + 18432 + (32 * rg + 16 * m + (lane & 15)) * PITB + (lane >> 4) * 16;
        #pragma unroll
        for (int k = 0; k < 4; k++) { ldsm4(aQh[m][k], ah + k * 32); ldsm4(aQl[m][k], al + k * 32); }
    }

    uint32_t boff = (lane & 7) * PITB + ((lane >> 3) & 1) * 16;
    float zr[4] = {0.f, 0.f, 0.f, 0.f};

    for (int jt = 0; jt < 32; jt++) {
        uint32_t cur = base + (jt & 1) * REG;
        uint32_t nxt = base + ((jt + 1) & 1) * REG;

        CP_WAIT0();
        __syncthreads();   // data(jt) visible; all warps done with nxt's old contents

        if (jt + 1 < 32) {
            for (int idx = t; idx < 128 * 8; idx += 256) {
                int row = idx >> 3, c8 = idx & 7;
                uint32_t off = row * PITB + c8 * 16;
                cp16(nxt + off,         &g_kth[br][b][(jt + 1) * 128 + row][c8 * 8]);
                cp16(nxt + 18432 + off, &g_ktl[br][b][(jt + 1) * 128 + row][c8 * 8]);
            }
            CP_COMMIT();
        }

        uint32_t kh0 = cur, kl0 = cur + 18432;

        #pragma unroll
        for (int np = 0; np < 4; np++) {
            float s4[2][2][4] = {};
            #pragma unroll
            for (int k = 0; k < 4; k++) {
                uint32_t bh[2][2], bl[2][2];
                #pragma unroll
                for (int p = 0; p < 2; p++) {
                    uint32_t cb = (64 * cg + 8 * (2 * np + p)) * PITB + boff + k * 32;
                    ldsm2(bh[p], kh0 + cb);
                    ldsm2(bl[p], kl0 + cb);
                }
                #pragma unroll
                for (int p = 0; p < 2; p++)
                    #pragma unroll
                    for (int m = 0; m < 2; m++) mma_bf16(s4[p][m], aQh[m][k], bh[p]);
                #pragma unroll
                for (int p = 0; p < 2; p++)
                    #pragma unroll
                    for (int m = 0; m < 2; m++) mma_bf16(s4[p][m], aQh[m][k], bl[p]);
                #pragma unroll
                for (int p = 0; p < 2; p++)
                    #pragma unroll
                    for (int m = 0; m < 2; m++) mma_bf16(s4[p][m], aQl[m][k], bh[p]);
            }
            #pragma unroll
            for (int p = 0; p < 2; p++)
                #pragma unroll
                for (int m = 0; m < 2; m++) {
                    zr[m * 2 + 0] += ex2f(s4[p][m][0] * L2E) + ex2f(s4[p][m][1] * L2E);
                    zr[m * 2 + 1] += ex2f(s4[p][m][2] * L2E) + ex2f(s4[p][m][3] * L2E);
                }
        }
    }

    #pragma unroll
    for (int q = 0; q < 4; q++) {
        zr[q] += __shfl_xor_sync(0xffffffffu, zr[q], 1);
        zr[q] += __shfl_xor_sync(0xffffffffu, zr[q], 2);
    }
    if ((lane & 3) == 0) {
        int rbase = 32 * rg + (lane >> 2);
        atomicAdd(&zbuf[rbase],      zr[0]);
        atomicAdd(&zbuf[rbase + 8],  zr[1]);
        atomicAdd(&zbuf[rbase + 16], zr[2]);
        atomicAdd(&zbuf[rbase + 24], zr[3]);
    }
    __syncthreads();
    if (t < 128) g_c[br][b][i0 + t] = __log2f(zbuf[t]);
}

// ---------------------------------------------------------------------------
// Kernel 3: O[j][c] = sum_i 2^(s[j][i]*L2E - c_i) * v[c][i]
// P stays in registers (acc m16n8 -> A m16k16 repack). One barrier per iter.
// ---------------------------------------------------------------------------
__global__ void __launch_bounds__(256, 2) pv_kernel() {
    extern __shared__ char dyn[];
    __shared__ float cs[2][64];

    int t = threadIdx.x, w = t >> 5, lane = t & 31;
    int j0 = blockIdx.x * 128, br = blockIdx.y, b = blockIdx.z;

    uint32_t base = smem_u32(dyn);

    for (int idx = t; idx < 128 * 8; idx += 256) {
        int row = idx >> 3, c8 = idx & 7;
        uint32_t off = row * PITB + c8 * 16;
        cp16(base + off,         &g_kth[br][b][j0 + row][c8 * 8]);
        cp16(base + 18432 + off, &g_ktl[br][b][j0 + row][c8 * 8]);
    }
    for (int idx = t; idx < 64 * 8; idx += 256) {
        int row = idx >> 3, c8 = idx & 7;
        uint32_t off = row * PITB + c8 * 16;
        cp16(base + REG + off,         &g_qth[br][b][row][c8 * 8]);
        cp16(base + REG + 9216 + off,  &g_qtl[br][b][row][c8 * 8]);
        cp16(base + REG + 18432 + off, &g_vh[br][b][row][c8 * 8]);
        cp16(base + REG + 27648 + off, &g_vl[br][b][row][c8 * 8]);
    }
    CP_COMMIT();
    if (t < 64) cs[0][t] = g_c[br][b][t];
    CP_WAIT0();
    __syncthreads();

    uint32_t aKh[4][4], aKl[4][4];
    {
        uint32_t ah = base +         (16 * w + (lane & 15)) * PITB + (lane >> 4) * 16;
        uint32_t al = base + 18432 + (16 * w + (lane & 15)) * PITB + (lane >> 4) * 16;
        #pragma unroll
        for (int k = 0; k < 4; k++) { ldsm4(aKh[k], ah + k * 32); ldsm4(aKl[k], al + k * 32); }
    }

    uint32_t boff = (lane & 7) * PITB + ((lane >> 3) & 1) * 16;
    float oacc[8][4] = {};

    for (int it = 0; it < 64; it++) {
        uint32_t cur = base + ((it & 1) ? 0 : REG);
        uint32_t nxt = base + ((it & 1) ? REG : 0);

        CP_WAIT0();
        __syncthreads();

        if (it + 1 < 64) {
            int i1 = (it + 1) * 64;
            for (int idx = t; idx < 64 * 8; idx += 256) {
                int row = idx >> 3, c8 = idx & 7;
                uint32_t off = row * PITB + c8 * 16;
                cp16(nxt + off,         &g_qth[br][b][i1 + row][c8 * 8]);
                cp16(nxt + 9216 + off,  &g_qtl[br][b][i1 + row][c8 * 8]);
                cp16(nxt + 18432 + off, &g_vh[br][b][row][i1 + c8 * 8]);
                cp16(nxt + 27648 + off, &g_vl[br][b][row][i1 + c8 * 8]);
            }
            CP_COMMIT();
            if (t < 64) cs[(it + 1) & 1][t] = g_c[br][b][i1 + t];
        }

        uint32_t qh0 = cur, ql0 = cur + 9216;
        uint32_t vh0 = cur + 18432, vl0 = cur + 27648;
        const float* csc = cs[it & 1];

        #pragma unroll
        for (int h = 0; h < 2; h++) {
            float s4[4][4] = {};
            #pragma unroll
            for (int k = 0; k < 4; k++) {
                uint32_t bh[4][2], bl[4][2];
                #pragma unroll
                for (int q = 0; q < 4; q++) {
                    uint32_t cb = (8 * (4 * h + q)) * PITB + boff + k * 32;
                    ldsm2(bh[q], qh0 + cb);
                    ldsm2(bl[q], ql0 + cb);
                }
                #pragma unroll
                for (int q = 0; q < 4; q++) mma_bf16(s4[q], aKh[k], bh[q]);
                #pragma unroll
                for (int q = 0; q < 4; q++) mma_bf16(s4[q], aKh[k], bl[q]);
                #pragma unroll
                for (int q = 0; q < 4; q++) mma_bf16(s4[q], aKl[k], bh[q]);
            }

            #pragma unroll
            for (int kc = 0; kc < 2; kc++) {
                uint32_t aP[4], aPl[4];
                #pragma unroll
                for (int qq = 0; qq < 2; qq++) {
                    int q = 2 * kc + qq;
                    int col = 8 * (4 * h + q) + 2 * (lane & 3);
                    float2 cc = *(float2*)&csc[col];
                    float p0 = ex2f(fmaf(s4[q][0], L2E, -cc.x));
                    float p1 = ex2f(fmaf(s4[q][1], L2E, -cc.y));
                    float p2 = ex2f(fmaf(s4[q][2], L2E, -cc.x));
                    float p3 = ex2f(fmaf(s4[q][3], L2E, -cc.y));
                    uint32_t u01 = cvtb2(p0, p1);
                    uint32_t u23 = cvtb2(p2, p3);
                    aP[qq * 2 + 0] = u01;
                    aP[qq * 2 + 1] = u23;
                    float h0 = __uint_as_float(u01 << 16);
                    float h1 = __uint_as_float(u01 & 0xFFFF0000u);
                    float h2 = __uint_as_float(u23 << 16);
                    float h3 = __uint_as_float(u23 & 0xFFFF0000u);
                    aPl[qq * 2 + 0] = cvtb2(p0 - h0, p1 - h1);
                    aPl[qq * 2 + 1] = cvtb2(p2 - h2, p3 - h3);
                }

                uint32_t kb = (uint32_t)(64 * h + 32 * kc);
                #pragma unroll
                for (int cg2 = 0; cg2 < 2; cg2++) {
                    uint32_t bVh[4][2], bVl[4][2];
                    #pragma unroll
                    for (int c4 = 0; c4 < 4; c4++) {
                        uint32_t cb = (8 * (4 * cg2 + c4)) * PITB + boff + kb;
                        ldsm2(bVh[c4], vh0 + cb);
                        ldsm2(bVl[c4], vl0 + cb);
                    }
                    #pragma unroll
                    for (int c4 = 0; c4 < 4; c4++) mma_bf16(oacc[4 * cg2 + c4], aP, bVh[c4]);
                    #pragma unroll
                    for (int c4 = 0; c4 < 4; c4++) mma_bf16(oacc[4 * cg2 + c4], aP, bVl[c4]);
                    #pragma unroll
                    for (int c4 = 0; c4 < 4; c4++) mma_bf16(oacc[4 * cg2 + c4], aPl, bVh[c4]);
                }
            }
        }
    }

    int jr = j0 + 16 * w + (lane >> 2);
    #pragma unroll
    for (int ct = 0; ct < 8; ct++) {
        int c0 = 8 * ct + 2 * (lane & 3);
        *(float2*)&g_ot[br][b][jr][c0]     = make_float2(oacc[ct][0], oacc[ct][1]);
        *(float2*)&g_ot[br][b][jr + 8][c0] = make_float2(oacc[ct][2], oacc[ct][3]);
    }
}

// ---------------------------------------------------------------------------
// Kernel 4: final fuse conv, reads g_ot with smem transpose staging
// ---------------------------------------------------------------------------
__global__ void __launch_bounds__(256, 2) final_kernel(const float* __restrict__ Wf,
                             const float* __restrict__ bf,
                             const float* __restrict__ g1p,
                             const float* __restrict__ g2p,
                             float* __restrict__ y) {
    extern __shared__ float smf[];
    float (*Wt)[64] = (float(*)[64])smf;                    // [128][64]
    float (*csm)[68] = (float(*)[68])(smf + 128 * 64);      // [128][68] padded
    float* bs = smf + 128 * 64 + 128 * 68;

    int t = threadIdx.x;
    int b = blockIdx.y;
    int n0 = blockIdx.x * 128;
    float gg1 = *g1p, gg2 = *g2p;

    for (int idx = t; idx < 64 * 128; idx += 256) {
        int o = idx >> 7, c = idx & 127;
        Wt[c][o] = Wf[idx];
    }
    if (t < 64) bs[t] = bf[t];
    __syncthreads();

    int tx = t & 15, ty = t >> 4;
    for (int nc = 0; nc < 128; nc += 64) {
        __syncthreads();
        for (int idx = t; idx < 2048; idx += 256) {
            int br2 = idx >> 10, rem = idx & 1023, n = rem >> 4, c4 = rem & 15;
            float4 v4 = *(const float4*)&g_ot[br2][b][n0 + nc + n][c4 * 4];
            float g = br2 ? gg2 : gg1;
            csm[br2 * 64 + c4 * 4 + 0][n] = v4.x * g;
            csm[br2 * 64 + c4 * 4 + 1][n] = v4.y * g;
            csm[br2 * 64 + c4 * 4 + 2][n] = v4.z * g;
            csm[br2 * 64 + c4 * 4 + 3][n] = v4.w * g;
        }
        __syncthreads();

        float acc[4][4] = {};
        #pragma unroll 8
        for (int c = 0; c < 128; c++) {
            float wv[4], xv[4];
            *(float4*)wv = *(float4*)&Wt[c][ty * 4];
            *(float4*)xv = *(float4*)&csm[c][tx * 4];
            #pragma unroll
            for (int i = 0; i < 4; i++)
                #pragma unroll
                for (int j = 0; j < 4; j++)
                    acc[i][j] += wv[i] * xv[j];
        }
        #pragma unroll
        for (int i = 0; i < 4; i++) {
            int o = ty * 4 + i;
            float bb = bs[o];
            float4 r = make_float4(acc[i][0] + bb, acc[i][1] + bb,
                                   acc[i][2] + bb, acc[i][3] + bb);
            *(float4*)&y[(size_t)b * 64 * NTOK + o * NTOK + n0 + nc + tx * 4] = r;
        }
    }
}

// ---------------------------------------------------------------------------
extern "C" void kernel_launch(void* const* d_in, const int* in_sizes, int n_in,
                              void* d_out, int out_size) {
    const float* x  = (const float*)d_in[0];
    const float* g1 = (const float*)d_in[13];
    const float* g2 = (const float*)d_in[14];
    const float* Wf = (const float*)d_in[15];
    const float* bf = (const float*)d_in[16];
    float* y = (float*)d_out;

    ProjArgs pa;
    for (int mi = 0; mi < 6; mi++) {
        pa.W[mi] = (const float*)d_in[1 + 2 * mi];
        pa.B[mi] = (const float*)d_in[2 + 2 * mi];
    }

    const int smP = (4096 + 4096 + 64) * 4 + 2 * 64 * PIT * 2;   // 51456
    const int smS = 2 * REG;                                     // 73728
    const int smV = 2 * REG;                                     // 73728
    const int smF = (128 * 64 + 128 * 68 + 64) * 4;              // 67840

    cudaFuncSetAttribute(proj_kernel,  cudaFuncAttributeMaxDynamicSharedMemorySize, smP);
    cudaFuncSetAttribute(stats_kernel, cudaFuncAttributeMaxDynamicSharedMemorySize, smS);
    cudaFuncSetAttribute(pv_kernel,    cudaFuncAttributeMaxDynamicSharedMemorySize, smV);
    cudaFuncSetAttribute(final_kernel, cudaFuncAttributeMaxDynamicSharedMemorySize, smF);

    proj_kernel<<<dim3(16, 4, 6), 256, smP>>>(x, pa);
    stats_kernel<<<dim3(32, 2, 4), 256, smS>>>();
    pv_kernel<<<dim3(32, 2, 4), 256, smV>>>();
    final_kernel<<<dim3(32, 4), 256, smF>>>(Wf, bf, g1, g2, y);
}